// round 12
// baseline (speedup 1.0000x reference)
#include <cuda_runtime.h>
#include <cuda_bf16.h>
#include <math.h>
#include <stdint.h>

#define TT 256
#define NROW 2048            // B*T
#define BN_EPS 1e-5f
#define GRID_PERS 296        // 148 SMs x 2 CTAs = one full wave

// scratch
__device__ float g_qkv[NROW * 192];    // only v-part (cols 128..191) is populated/used
__device__ float g_proj[NROW * 128];   // qA|kA per row  ({q,k}@attn_w1)
__device__ float g_w2p[32 * 64];       // tpr_w2 @ attn_w1
__device__ float g_b1a[64];            // tpr_b2 @ attn_w1 + attn_b1

// ---------------------------------------------------------------------------
// Fused prelude: blocks 0..127 -> qkv+proj for 16 rows each; block 128 -> w2p
// ---------------------------------------------------------------------------
__global__ __launch_bounds__(256) void prelude_kernel(
    const float* __restrict__ x, const float* __restrict__ w_qkv,
    const float* __restrict__ aw1, const float* __restrict__ tpr_w2,
    const float* __restrict__ tpr_b2, const float* __restrict__ ab1)
{
    const int tid = threadIdx.x;

    if (blockIdx.x == 128) {
        // ---- W2P = tpr_w2 @ attn_w1 ; b1a = tpr_b2 @ attn_w1 + attn_b1 ----
        if (tid < 64) {
            const int c = tid;
            for (int h = 0; h < 32; h++) {
                float acc = 0.f;
#pragma unroll 8
                for (int d = 0; d < 64; d++)
                    acc += tpr_w2[h * 64 + d] * aw1[d * 64 + c];
                g_w2p[h * 64 + c] = acc;
            }
            float accb = ab1[c];
#pragma unroll 8
            for (int d = 0; d < 64; d++) accb += tpr_b2[d] * aw1[d * 64 + c];
            g_b1a[c] = accb;
        }
        return;
    }

    __shared__ float xs[16 * 128];     // 16 rows of x
    __shared__ float qs[16 * 192];     // 16 rows of qkv
    const int r0 = blockIdx.x * 16;

    // stage x rows
    for (int idx = tid; idx < 16 * 128; idx += 256)
        xs[idx] = x[(size_t)r0 * 128 + idx];
    __syncthreads();

    // qkv: 192 cols, w_qkv read ONCE per block
    if (tid < 192) {
        const int col = tid;
        float acc[16];
#pragma unroll
        for (int rr = 0; rr < 16; rr++) acc[rr] = 0.f;
        for (int d = 0; d < 128; d++) {
            const float wv = w_qkv[d * 192 + col];
#pragma unroll
            for (int rr = 0; rr < 16; rr++)
                acc[rr] += xs[rr * 128 + d] * wv;
        }
#pragma unroll
        for (int rr = 0; rr < 16; rr++) {
            qs[rr * 192 + col] = acc[rr];
            if (col >= 128)                       // only v needed downstream
                g_qkv[(size_t)(r0 + rr) * 192 + col] = acc[rr];
        }
    }
    __syncthreads();

    // proj: qA|kA = {q,k} @ aw1 ; aw1 read once per block (L1/L2 resident)
    {
        const int col = tid & 63;
        const int half = (tid >> 6) & 1;          // 0 = q, 1 = k
        const int rg = tid >> 7;                  // row group (8 rows)
        float acc8[8];
#pragma unroll
        for (int rr = 0; rr < 8; rr++) acc8[rr] = 0.f;
        for (int d = 0; d < 64; d++) {
            const float av = aw1[d * 64 + col];
#pragma unroll
            for (int rr = 0; rr < 8; rr++)
                acc8[rr] += qs[(rg * 8 + rr) * 192 + half * 64 + d] * av;
        }
#pragma unroll
        for (int rr = 0; rr < 8; rr++)
            g_proj[(size_t)(r0 + rg * 8 + rr) * 128 + half * 64 + col] = acc8[rr];
    }
}

// ---------------------------------------------------------------------------
// helpers
// ---------------------------------------------------------------------------
__device__ __forceinline__ void mma_bf16(float* d, const uint32_t* a,
                                         uint32_t b0, uint32_t b1) {
    asm volatile(
        "mma.sync.aligned.m16n8k16.row.col.f32.bf16.bf16.f32 "
        "{%0,%1,%2,%3}, {%4,%5,%6,%7}, {%8,%9}, {%0,%1,%2,%3};"
        : "+f"(d[0]), "+f"(d[1]), "+f"(d[2]), "+f"(d[3])
        : "r"(a[0]), "r"(a[1]), "r"(a[2]), "r"(a[3]), "r"(b0), "r"(b1));
}

__device__ __forceinline__ void ldsm_x4(uint32_t& r0, uint32_t& r1,
                                        uint32_t& r2, uint32_t& r3, uint32_t addr) {
    asm volatile("ldmatrix.sync.aligned.m8n8.x4.shared.b16 {%0,%1,%2,%3}, [%4];"
                 : "=r"(r0), "=r"(r1), "=r"(r2), "=r"(r3) : "r"(addr));
}

#define BAR_ARRIVE(id) asm volatile("bar.arrive %0, %1;" :: "r"(id), "r"(256) : "memory")
#define BAR_SYNC(id)   asm volatile("bar.sync %0, %1;"   :: "r"(id), "r"(256) : "memory")

__device__ __forceinline__ uint32_t b2u(__nv_bfloat162 v) {
    return *reinterpret_cast<uint32_t*>(&v);
}

__device__ __forceinline__ void split2(float x, float y, uint32_t& hi, uint32_t& lo) {
    __nv_bfloat16 hx = __float2bfloat16_rn(x);
    __nv_bfloat16 hy = __float2bfloat16_rn(y);
    float rx = x - __bfloat162float(hx);
    float ry = y - __bfloat162float(hy);
    __nv_bfloat162 h2; h2.x = hx; h2.y = hy;
    hi = b2u(h2);
    lo = b2u(__floats2bfloat162_rn(rx, ry));
}

__device__ __forceinline__ void split1(float x, __nv_bfloat16& hi, __nv_bfloat16& lo) {
    hi = __float2bfloat16_rn(x);
    lo = __float2bfloat16_rn(x - __bfloat162float(hi));
}

// 4 n-tiles, 3-term bf16x3 split, dependency distance 4 (12 MMAs)
#define MMA_GROUP4(ACC, T0, AH, AL, WHI, WLO, STRIDE, KOFF)                       \
    do {                                                                          \
        uint32_t bh[8], bl[8];                                                    \
        ldsm_x4(bh[0], bh[1], bh[2], bh[3],                                       \
                WHI + (uint32_t)((((T0) * 8 + brow) * (STRIDE)) + (KOFF) + bcol) * 2u); \
        ldsm_x4(bh[4], bh[5], bh[6], bh[7],                                       \
                WHI + (uint32_t)(((((T0) + 2) * 8 + brow) * (STRIDE)) + (KOFF) + bcol) * 2u); \
        ldsm_x4(bl[0], bl[1], bl[2], bl[3],                                       \
                WLO + (uint32_t)((((T0) * 8 + brow) * (STRIDE)) + (KOFF) + bcol) * 2u); \
        ldsm_x4(bl[4], bl[5], bl[6], bl[7],                                       \
                WLO + (uint32_t)(((((T0) + 2) * 8 + brow) * (STRIDE)) + (KOFF) + bcol) * 2u); \
        mma_bf16(ACC[(T0) + 0], AH, bh[0], bh[1]);                                \
        mma_bf16(ACC[(T0) + 1], AH, bh[2], bh[3]);                                \
        mma_bf16(ACC[(T0) + 2], AH, bh[4], bh[5]);                                \
        mma_bf16(ACC[(T0) + 3], AH, bh[6], bh[7]);                                \
        mma_bf16(ACC[(T0) + 0], AH, bl[0], bl[1]);                                \
        mma_bf16(ACC[(T0) + 1], AH, bl[2], bl[3]);                                \
        mma_bf16(ACC[(T0) + 2], AH, bl[4], bl[5]);                                \
        mma_bf16(ACC[(T0) + 3], AH, bl[6], bl[7]);                                \
        mma_bf16(ACC[(T0) + 0], AL, bh[0], bh[1]);                                \
        mma_bf16(ACC[(T0) + 1], AL, bh[2], bh[3]);                                \
        mma_bf16(ACC[(T0) + 2], AL, bh[4], bh[5]);                                \
        mma_bf16(ACC[(T0) + 3], AL, bh[6], bh[7]);                                \
    } while (0)

// ---------------------------------------------------------------------------
// Shared memory byte offsets (16B aligned)
// ---------------------------------------------------------------------------
#define SO_WRE_HI 0          // [64][40] bf16  W2T^T
#define SO_WRE_LO 5120
#define SO_WS1_HI 10240      // [64][40] bf16  W2P^T
#define SO_WS1_LO 15360
#define SO_WAT_HI 20480      // [64][72] bf16  W2A^T
#define SO_WAT_LO 29696
#define SO_S1X_HI 38912      // [64][72] bf16  S1 exchange
#define SO_S1X_LO 48128
#define SO_CL     38912      // combine partials (alias S1X; used post-loop)
#define SO_CA     47232      // 32*65 fp32 each
#define SO_RT_HI  57344      // [64][24] bf16  r tile (k padded 16)
#define SO_RT_LO  60416
#define SO_W1T_HI 63488      // [32][24] bf16  BN-folded W1^T
#define SO_W1T_LO 65024
#define SO_VJ     66560      // [64][36] fp32  vj cols 0..31 exchange
#define SO_B1F    75776      // 32 fp32
#define SO_B2F    75904      // 64
#define SO_B1A    76160      // 64
#define SO_QA     76416      // 64
#define SMEM_BYTES 76672

__global__ __launch_bounds__(256, 2) void va_kernel(
    const float* __restrict__ r,
    const float* __restrict__ tpr_w1, const float* __restrict__ tpr_b1,
    const float* __restrict__ bn_g, const float* __restrict__ bn_b,
    const float* __restrict__ bn_m, const float* __restrict__ bn_v,
    const float* __restrict__ tpr_w2, const float* __restrict__ tpr_b2,
    const float* __restrict__ aw2, float* __restrict__ out)
{
    extern __shared__ __align__(16) char sb[];
    __nv_bfloat16* RT_HI  = (__nv_bfloat16*)(sb + SO_RT_HI);
    __nv_bfloat16* RT_LO  = (__nv_bfloat16*)(sb + SO_RT_LO);
    __nv_bfloat16* W1T_HI = (__nv_bfloat16*)(sb + SO_W1T_HI);
    __nv_bfloat16* W1T_LO = (__nv_bfloat16*)(sb + SO_W1T_LO);
    __nv_bfloat16* WRE_HI = (__nv_bfloat16*)(sb + SO_WRE_HI);
    __nv_bfloat16* WRE_LO = (__nv_bfloat16*)(sb + SO_WRE_LO);
    __nv_bfloat16* WS1_HI = (__nv_bfloat16*)(sb + SO_WS1_HI);
    __nv_bfloat16* WS1_LO = (__nv_bfloat16*)(sb + SO_WS1_LO);
    __nv_bfloat16* WAT_HI = (__nv_bfloat16*)(sb + SO_WAT_HI);
    __nv_bfloat16* WAT_LO = (__nv_bfloat16*)(sb + SO_WAT_LO);
    __nv_bfloat16* S1X_HI = (__nv_bfloat16*)(sb + SO_S1X_HI);
    __nv_bfloat16* S1X_LO = (__nv_bfloat16*)(sb + SO_S1X_LO);
    float* CL   = (float*)(sb + SO_CL);
    float* CA   = (float*)(sb + SO_CA);
    float* VJ   = (float*)(sb + SO_VJ);
    float* B1F  = (float*)(sb + SO_B1F);
    float* B2F  = (float*)(sb + SO_B2F);
    float* B1A  = (float*)(sb + SO_B1A);
    float* QA   = (float*)(sb + SO_QA);

    const int tid = threadIdx.x;
    const int wid = tid >> 5, lane = tid & 31;
    const int gid = lane >> 2, tig = lane & 3;
    const int arow = lane & 7, asel = lane >> 3;

    // ---- stage weights ONCE per persistent CTA ----
    for (int idx = tid; idx < 64 * 24; idx += 256) { RT_HI[idx] = __nv_bfloat16(0.f); RT_LO[idx] = __nv_bfloat16(0.f); }
    for (int idx = tid; idx < 32 * 24; idx += 256) { W1T_HI[idx] = __nv_bfloat16(0.f); W1T_LO[idx] = __nv_bfloat16(0.f); }
    if (tid < 32) {
        float sc = bn_g[tid] * rsqrtf(bn_v[tid] + BN_EPS);
        B1F[tid] = (tpr_b1[tid] - bn_m[tid]) * sc + bn_b[tid];
    }
    if (tid < 64) {
        B2F[tid] = tpr_b2[tid];
        B1A[tid] = g_b1a[tid];
    }
    __syncthreads();
    for (int idx = tid; idx < 288; idx += 256) {      // BN-folded W1^T
        const int d = idx >> 5, n = idx & 31;
        const float sc = bn_g[n] * rsqrtf(bn_v[n] + BN_EPS);
        __nv_bfloat16 hi, lo;
        split1(tpr_w1[idx] * sc, hi, lo);
        W1T_HI[n * 24 + d] = hi;
        W1T_LO[n * 24 + d] = lo;
    }
    for (int idx = tid; idx < 2048; idx += 256) {     // W2T^T, W2P^T (stride 40)
        const int n = idx >> 5, k = idx & 31;
        __nv_bfloat16 hi, lo;
        split1(tpr_w2[k * 64 + n], hi, lo);
        WRE_HI[n * 40 + k] = hi; WRE_LO[n * 40 + k] = lo;
        split1(g_w2p[k * 64 + n], hi, lo);
        WS1_HI[n * 40 + k] = hi; WS1_LO[n * 40 + k] = lo;
    }
    for (int idx = tid; idx < 4096; idx += 256) {     // W2A^T (stride 72)
        const int n = idx >> 6, k = idx & 63;
        __nv_bfloat16 hi, lo;
        split1(aw2[k * 64 + n], hi, lo);
        WAT_HI[n * 72 + k] = hi; WAT_LO[n * 72 + k] = lo;
    }

    const int wmod = wid & 3;            // m-tile (warps w and w+4 share it)
    const int nq = wid >> 2;             // n-half owner for Sim phase
    const int m0 = wmod * 16;
    const int r0 = m0 + gid;
    const int brow = arow + (asel >> 1) * 8;
    const int bcol = (asel & 1) * 8;
    const int aoff24 = (m0 + arow + (asel & 1) * 8) * 24 + (asel >> 1) * 8;
    const int aoff72 = (m0 + arow + (asel & 1) * 8) * 72 + (asel >> 1) * 8;

    const uint32_t RThi_a  = (uint32_t)__cvta_generic_to_shared(RT_HI);
    const uint32_t RTlo_a  = (uint32_t)__cvta_generic_to_shared(RT_LO);
    const uint32_t W1Thi_a = (uint32_t)__cvta_generic_to_shared(W1T_HI);
    const uint32_t W1Tlo_a = (uint32_t)__cvta_generic_to_shared(W1T_LO);
    const uint32_t WS1hi_a = (uint32_t)__cvta_generic_to_shared(WS1_HI);
    const uint32_t WS1lo_a = (uint32_t)__cvta_generic_to_shared(WS1_LO);
    const uint32_t WREhi_a = (uint32_t)__cvta_generic_to_shared(WRE_HI);
    const uint32_t WRElo_a = (uint32_t)__cvta_generic_to_shared(WRE_LO);
    const uint32_t WAThi_a = (uint32_t)__cvta_generic_to_shared(WAT_HI) + (uint32_t)(nq * 32 * 72 * 2);
    const uint32_t WATlo_a = (uint32_t)__cvta_generic_to_shared(WAT_LO) + (uint32_t)(nq * 32 * 72 * 2);
    const uint32_t S1Xhi_a = (uint32_t)__cvta_generic_to_shared(S1X_HI);
    const uint32_t S1Xlo_a = (uint32_t)__cvta_generic_to_shared(S1X_LO);

    for (int row = blockIdx.x; row < NROW; row += GRID_PERS) {
        const int b = row >> 8;
        const float* rrow = r + (size_t)row * (TT * 9);

        // ---- stage QA + r tile 0 (prev row's reads all barrier-protected) ----
        if (tid < 64) QA[tid] = g_proj[row * 128 + tid];
        float4 rpre;
        if (tid < 144) rpre = ((const float4*)rrow)[tid];
        if (tid < 144) {
            const int e0 = tid * 4;
#pragma unroll
            for (int u = 0; u < 4; u++) {
                const int e = e0 + u, j = e / 9, d = e - j * 9;
                __nv_bfloat16 hi, lo;
                split1(((const float*)&rpre)[u], hi, lo);
                RT_HI[j * 24 + d] = hi;
                RT_LO[j * 24 + d] = lo;
            }
        }
        __syncthreads();

        float l8[8], a8[8];
#pragma unroll
        for (int s = 0; s < 8; s++) { l8[s] = 0.f; a8[s] = 0.f; }

        for (int jt = 0; jt < 4; jt++) {
            const int j0 = jt * 64;

            // ---- Phase A (regs, every warp): H = relu(r @ W1F + B1F) ----
            uint32_t Hhi[2][4], Hlo[2][4];
            {
                uint32_t rahi[4], ralo[4];
                ldsm_x4(rahi[0], rahi[1], rahi[2], rahi[3], RThi_a + (uint32_t)aoff24 * 2u);
                ldsm_x4(ralo[0], ralo[1], ralo[2], ralo[3], RTlo_a + (uint32_t)aoff24 * 2u);
                // prefetch next r tile while MMAs run
                if (jt < 3 && tid < 144)
                    rpre = ((const float4*)(rrow + (j0 + 64) * 9))[tid];
                float accA[4][4];
#pragma unroll
                for (int t = 0; t < 4; t++)
#pragma unroll
                    for (int u = 0; u < 4; u++) accA[t][u] = 0.f;
                MMA_GROUP4(accA, 0, rahi, ralo, W1Thi_a, W1Tlo_a, 24, 0);
#pragma unroll
                for (int ks = 0; ks < 2; ks++) {
                    const int t0 = 2 * ks, t1 = 2 * ks + 1;
                    const float2 bb0 = *(const float2*)(B1F + t0 * 8 + 2 * tig);
                    const float2 bb1 = *(const float2*)(B1F + t1 * 8 + 2 * tig);
                    split2(fmaxf(accA[t0][0] + bb0.x, 0.f), fmaxf(accA[t0][1] + bb0.y, 0.f),
                           Hhi[ks][0], Hlo[ks][0]);
                    split2(fmaxf(accA[t0][2] + bb0.x, 0.f), fmaxf(accA[t0][3] + bb0.y, 0.f),
                           Hhi[ks][1], Hlo[ks][1]);
                    split2(fmaxf(accA[t1][0] + bb1.x, 0.f), fmaxf(accA[t1][1] + bb1.y, 0.f),
                           Hhi[ks][2], Hlo[ks][2]);
                    split2(fmaxf(accA[t1][2] + bb1.x, 0.f), fmaxf(accA[t1][3] + bb1.y, 0.f),
                           Hhi[ks][3], Hlo[ks][3]);
                }
            }

            float accD[4][4];
#pragma unroll
            for (int t = 0; t < 4; t++)
#pragma unroll
                for (int u = 0; u < 4; u++) accD[t][u] = 0.f;
            float vjk[4][4];                   // warps 4-7: vj cols 32..63

            if (wid < 4) {
                // ---- warps 0-3: S1 = relu(H@W2P + qa - ka + b1a) ----
                float accS[8][4];
#pragma unroll
                for (int t = 0; t < 8; t++)
#pragma unroll
                    for (int u = 0; u < 4; u++) accS[t][u] = 0.f;
#pragma unroll
                for (int g = 0; g < 2; g++)
#pragma unroll
                    for (int ks = 0; ks < 2; ks++)
                        MMA_GROUP4(accS, g * 4, Hhi[ks], Hlo[ks], WS1hi_a, WS1lo_a, 40, ks * 16);
                const float* ka0p = &g_proj[(b * TT + j0 + r0) * 128 + 64];
                const float* ka1p = &g_proj[(b * TT + j0 + r0 + 8) * 128 + 64];
                uint32_t s1hi[4][4], s1lo[4][4];
#pragma unroll
                for (int kg = 0; kg < 4; kg++) {
#pragma unroll
                    for (int half = 0; half < 2; half++) {
                        const int tt = 2 * kg + half;
                        const int c = tt * 8 + 2 * tig;
                        const float2 qa2 = *(const float2*)(QA + c);
                        const float2 ba2 = *(const float2*)(B1A + c);
                        const float2 ka0 = *(const float2*)(ka0p + c);
                        const float2 ka1 = *(const float2*)(ka1p + c);
                        const float s00 = fmaxf(accS[tt][0] + qa2.x - ka0.x + ba2.x, 0.f);
                        const float s01 = fmaxf(accS[tt][1] + qa2.y - ka0.y + ba2.y, 0.f);
                        const float s10 = fmaxf(accS[tt][2] + qa2.x - ka1.x + ba2.x, 0.f);
                        const float s11 = fmaxf(accS[tt][3] + qa2.y - ka1.y + ba2.y, 0.f);
                        uint32_t hi0, lo0, hi1, lo1;
                        split2(s00, s01, hi0, lo0);
                        split2(s10, s11, hi1, lo1);
                        s1hi[kg][half * 2] = hi0;     s1lo[kg][half * 2] = lo0;
                        s1hi[kg][half * 2 + 1] = hi1; s1lo[kg][half * 2 + 1] = lo1;
                        *(uint32_t*)(S1X_HI + r0 * 72 + c) = hi0;
                        *(uint32_t*)(S1X_LO + r0 * 72 + c) = lo0;
                        *(uint32_t*)(S1X_HI + (r0 + 8) * 72 + c) = hi1;
                        *(uint32_t*)(S1X_LO + (r0 + 8) * 72 + c) = lo1;
                    }
                }
                BAR_ARRIVE(1);                 // S1X published
                // Sim immediately from own fragments — no wait on warps 4-7
#pragma unroll
                for (int ks = 0; ks < 4; ks++)
                    MMA_GROUP4(accD, 0, s1hi[ks], s1lo[ks], WAThi_a, WATlo_a, 72, ks * 16);
                BAR_SYNC(2);                   // wait for VJ
            } else {
                // ---- warps 4-7: RE = H@W2T + b2f ; vj = RE + vg ----
                float accR[8][4];
#pragma unroll
                for (int t = 0; t < 8; t++)
#pragma unroll
                    for (int u = 0; u < 4; u++) accR[t][u] = 0.f;
#pragma unroll
                for (int g = 0; g < 2; g++)
#pragma unroll
                    for (int ks = 0; ks < 2; ks++)
                        MMA_GROUP4(accR, g * 4, Hhi[ks], Hlo[ks], WREhi_a, WRElo_a, 40, ks * 16);
                const float* v0p = &g_qkv[(b * TT + j0 + r0) * 192 + 128];
                const float* v1p = &g_qkv[(b * TT + j0 + r0 + 8) * 192 + 128];
#pragma unroll
                for (int tt = 0; tt < 8; tt++) {
                    const int c = tt * 8 + 2 * tig;
                    const float2 bf2 = *(const float2*)(B2F + c);
                    const float2 vg0 = *(const float2*)(v0p + c);
                    const float2 vg1 = *(const float2*)(v1p + c);
                    const float j00 = accR[tt][0] + bf2.x + vg0.x;
                    const float j01 = accR[tt][1] + bf2.y + vg0.y;
                    const float j10 = accR[tt][2] + bf2.x + vg1.x;
                    const float j11 = accR[tt][3] + bf2.y + vg1.y;
                    if (tt < 4) {            // cols 0..31 -> smem for warps 0-3
                        *(float2*)(VJ + r0 * 36 + c) = make_float2(j00, j01);
                        *(float2*)(VJ + (r0 + 8) * 36 + c) = make_float2(j10, j11);
                    } else {                 // cols 32..63 stay local
                        vjk[tt - 4][0] = j00; vjk[tt - 4][1] = j01;
                        vjk[tt - 4][2] = j10; vjk[tt - 4][3] = j11;
                    }
                }
                BAR_ARRIVE(2);                 // VJ published
                BAR_SYNC(1);                   // wait for S1X
                uint32_t s1hi[4][4], s1lo[4][4];
#pragma unroll
                for (int ks = 0; ks < 4; ks++) {
                    ldsm_x4(s1hi[ks][0], s1hi[ks][1], s1hi[ks][2], s1hi[ks][3],
                            S1Xhi_a + (uint32_t)(aoff72 + ks * 16) * 2u);
                    ldsm_x4(s1lo[ks][0], s1lo[ks][1], s1lo[ks][2], s1lo[ks][3],
                            S1Xlo_a + (uint32_t)(aoff72 + ks * 16) * 2u);
                }
#pragma unroll
                for (int ks = 0; ks < 4; ks++)
                    MMA_GROUP4(accD, 0, s1hi[ks], s1lo[ks], WAThi_a, WATlo_a, 72, ks * 16);
            }

            // ---- softmax accumulate in fragment layout ----
#pragma unroll
            for (int tt = 0; tt < 4; tt++) {
                float vj00, vj01, vj10, vj11;
                if (wid < 4) {
                    const int c = tt * 8 + 2 * tig;
                    const float2 a0v = *(const float2*)(VJ + r0 * 36 + c);
                    const float2 a1v = *(const float2*)(VJ + (r0 + 8) * 36 + c);
                    vj00 = a0v.x; vj01 = a0v.y; vj10 = a1v.x; vj11 = a1v.y;
                } else {
                    vj00 = vjk[tt][0]; vj01 = vjk[tt][1];
                    vj10 = vjk[tt][2]; vj11 = vjk[tt][3];
                }
                const float e00 = __expf(accD[tt][0]);
                const float e01 = __expf(accD[tt][1]);
                const float e10 = __expf(accD[tt][2]);
                const float e11 = __expf(accD[tt][3]);
                l8[tt * 2 + 0] += e00 + e10;
                l8[tt * 2 + 1] += e01 + e11;
                a8[tt * 2 + 0] += e00 * vj00 + e10 * vj10;
                a8[tt * 2 + 1] += e01 * vj01 + e11 * vj11;
            }

            // ---- store next r tile (all Phase-A RT reads provably done:
            //      each group's bar.sync waited on the other's post-Phase-A arrive) ----
            if (jt < 3 && tid < 144) {
                const int e0 = tid * 4;
#pragma unroll
                for (int u = 0; u < 4; u++) {
                    const int e = e0 + u, j = e / 9, d = e - j * 9;
                    __nv_bfloat16 hi, lo;
                    split1(((const float*)&rpre)[u], hi, lo);
                    RT_HI[j * 24 + d] = hi;
                    RT_LO[j * 24 + d] = lo;
                }
            }
            __syncthreads();   // guards RT STS vs next ldsm + S1X/VJ reuse
        }

        // ---- cross-warp combine (CL/CA alias S1X space) ----
        {
            const int p = wmod * 8 + gid;
#pragma unroll
            for (int tt = 0; tt < 4; tt++) {
#pragma unroll
                for (int u = 0; u < 2; u++) {
                    const int c = nq * 32 + tt * 8 + 2 * tig + u;
                    CL[p * 65 + c] = l8[tt * 2 + u];
                    CA[p * 65 + c] = a8[tt * 2 + u];
                }
            }
        }
        __syncthreads();
        if (tid < 64) {
            float L = 0.f, A = 0.f;
#pragma unroll
            for (int pp = 0; pp < 32; pp++) {
                L += CL[pp * 65 + tid];
                A += CA[pp * 65 + tid];
            }
            out[row * 64 + tid] = A / L;
        }
        __syncthreads();           // CL/CA reads done before next row's S1X writes
    }
}

// ---------------------------------------------------------------------------
extern "C" void kernel_launch(void* const* d_in, const int* in_sizes, int n_in,
                              void* d_out, int out_size) {
    (void)in_sizes; (void)n_in; (void)out_size;
    const float* x      = (const float*)d_in[0];
    const float* r      = (const float*)d_in[1];
    const float* w_qkv  = (const float*)d_in[2];
    const float* tpr_w1 = (const float*)d_in[3];
    const float* tpr_b1 = (const float*)d_in[4];
    const float* bn_g   = (const float*)d_in[5];
    const float* bn_b   = (const float*)d_in[6];
    const float* bn_m   = (const float*)d_in[7];
    const float* bn_v   = (const float*)d_in[8];
    const float* tpr_w2 = (const float*)d_in[9];
    const float* tpr_b2 = (const float*)d_in[10];
    const float* aw1    = (const float*)d_in[11];
    const float* ab1    = (const float*)d_in[12];
    const float* aw2    = (const float*)d_in[13];
    float* out = (float*)d_out;

    cudaFuncSetAttribute(va_kernel, cudaFuncAttributeMaxDynamicSharedMemorySize,
                         SMEM_BYTES);

    prelude_kernel<<<129, 256>>>(x, w_qkv, aw1, tpr_w2, tpr_b2, ab1);
    va_kernel<<<GRID_PERS, 256, SMEM_BYTES>>>(r, tpr_w1, tpr_b1, bn_g, bn_b, bn_m,
                                              bn_v, tpr_w2, tpr_b2, aw2, out);
}

// round 13
// speedup vs baseline: 1.1958x; 1.1958x over previous
#include <cuda_runtime.h>
#include <cuda_bf16.h>
#include <math.h>
#include <stdint.h>

#define TT 256
#define NROW 2048            // B*T
#define BN_EPS 1e-5f
#define GRID_PERS 296        // 148 SMs x 2 CTAs = one full wave

// scratch
__device__ float g_qkv[NROW * 192];    // only v-part (cols 128..191) is populated/used
__device__ float g_proj[NROW * 128];   // qA|kA per row  ({q,k}@attn_w1)
__device__ float g_w2p[32 * 64];       // tpr_w2 @ attn_w1
__device__ float g_b1a[64];            // tpr_b2 @ attn_w1 + attn_b1

// ---------------------------------------------------------------------------
// Fused prelude: blocks 0..127 -> qkv+proj for 16 rows each; block 128 -> w2p
// ---------------------------------------------------------------------------
__global__ __launch_bounds__(256) void prelude_kernel(
    const float* __restrict__ x, const float* __restrict__ w_qkv,
    const float* __restrict__ aw1, const float* __restrict__ tpr_w2,
    const float* __restrict__ tpr_b2, const float* __restrict__ ab1)
{
    const int tid = threadIdx.x;

    __shared__ float sA[4096];         // aw1 (block 128) | unused others
    __shared__ float xs[16 * 128];     // 16 rows of x    | w2s (block 128, first 2048)
    __shared__ float qs[16 * 192];     // 16 rows of qkv

    if (blockIdx.x == 128) {
        // ---- W2P = tpr_w2 @ attn_w1 ; b1a = tpr_b2 @ attn_w1 + attn_b1 ----
        float* w2s = xs;               // reuse xs region (2048 floats)
        for (int i = tid; i < 2048; i += 256) w2s[i] = tpr_w2[i];
        for (int i = tid; i < 4096; i += 256) sA[i] = aw1[i];
        __syncthreads();
#pragma unroll
        for (int kk = 0; kk < 8; kk++) {
            const int idx = tid + kk * 256;        // 0..2047
            const int h = idx >> 6, c = idx & 63;
            float acc = 0.f;
#pragma unroll 8
            for (int d = 0; d < 64; d++) acc += w2s[h * 64 + d] * sA[d * 64 + c];
            g_w2p[idx] = acc;
        }
        if (tid < 64) {
            float accb = ab1[tid];
#pragma unroll 8
            for (int d = 0; d < 64; d++) accb += tpr_b2[d] * sA[d * 64 + tid];
            g_b1a[tid] = accb;
        }
        return;
    }

    const int r0 = blockIdx.x * 16;

    // stage x rows
    for (int idx = tid; idx < 16 * 128; idx += 256)
        xs[idx] = x[(size_t)r0 * 128 + idx];
    __syncthreads();

    // qkv: 192 cols, w_qkv read ONCE per block
    if (tid < 192) {
        const int col = tid;
        float acc[16];
#pragma unroll
        for (int rr = 0; rr < 16; rr++) acc[rr] = 0.f;
#pragma unroll 8
        for (int d = 0; d < 128; d++) {
            const float wv = w_qkv[d * 192 + col];
#pragma unroll
            for (int rr = 0; rr < 16; rr++)
                acc[rr] += xs[rr * 128 + d] * wv;
        }
#pragma unroll
        for (int rr = 0; rr < 16; rr++) {
            qs[rr * 192 + col] = acc[rr];
            if (col >= 128)                       // only v needed downstream
                g_qkv[(size_t)(r0 + rr) * 192 + col] = acc[rr];
        }
    }
    __syncthreads();

    // proj: qA|kA = {q,k} @ aw1 ; aw1 read once per block (L1/L2 resident)
    {
        const int col = tid & 63;
        const int half = (tid >> 6) & 1;          // 0 = q, 1 = k
        const int rg = tid >> 7;                  // row group (8 rows)
        float acc8[8];
#pragma unroll
        for (int rr = 0; rr < 8; rr++) acc8[rr] = 0.f;
#pragma unroll 8
        for (int d = 0; d < 64; d++) {
            const float av = aw1[d * 64 + col];
#pragma unroll
            for (int rr = 0; rr < 8; rr++)
                acc8[rr] += qs[(rg * 8 + rr) * 192 + half * 64 + d] * av;
        }
#pragma unroll
        for (int rr = 0; rr < 8; rr++)
            g_proj[(size_t)(r0 + rg * 8 + rr) * 128 + half * 64 + col] = acc8[rr];
    }
}

// ---------------------------------------------------------------------------
// helpers
// ---------------------------------------------------------------------------
__device__ __forceinline__ void mma_bf16(float* d, const uint32_t* a,
                                         uint32_t b0, uint32_t b1) {
    asm volatile(
        "mma.sync.aligned.m16n8k16.row.col.f32.bf16.bf16.f32 "
        "{%0,%1,%2,%3}, {%4,%5,%6,%7}, {%8,%9}, {%0,%1,%2,%3};"
        : "+f"(d[0]), "+f"(d[1]), "+f"(d[2]), "+f"(d[3])
        : "r"(a[0]), "r"(a[1]), "r"(a[2]), "r"(a[3]), "r"(b0), "r"(b1));
}

__device__ __forceinline__ void ldsm_x4(uint32_t& r0, uint32_t& r1,
                                        uint32_t& r2, uint32_t& r3, uint32_t addr) {
    asm volatile("ldmatrix.sync.aligned.m8n8.x4.shared.b16 {%0,%1,%2,%3}, [%4];"
                 : "=r"(r0), "=r"(r1), "=r"(r2), "=r"(r3) : "r"(addr));
}

#define BAR_ARRIVE(id) asm volatile("bar.arrive %0, %1;" :: "r"(id), "r"(256) : "memory")
#define BAR_SYNC(id)   asm volatile("bar.sync %0, %1;"   :: "r"(id), "r"(256) : "memory")

__device__ __forceinline__ uint32_t b2u(__nv_bfloat162 v) {
    return *reinterpret_cast<uint32_t*>(&v);
}

__device__ __forceinline__ void split2(float x, float y, uint32_t& hi, uint32_t& lo) {
    __nv_bfloat16 hx = __float2bfloat16_rn(x);
    __nv_bfloat16 hy = __float2bfloat16_rn(y);
    float rx = x - __bfloat162float(hx);
    float ry = y - __bfloat162float(hy);
    __nv_bfloat162 h2; h2.x = hx; h2.y = hy;
    hi = b2u(h2);
    lo = b2u(__floats2bfloat162_rn(rx, ry));
}

__device__ __forceinline__ void split1(float x, __nv_bfloat16& hi, __nv_bfloat16& lo) {
    hi = __float2bfloat16_rn(x);
    lo = __float2bfloat16_rn(x - __bfloat162float(hi));
}

// 4 n-tiles, 3-term bf16x3 split, dependency distance 4 (12 MMAs)
#define MMA_GROUP4(ACC, T0, AH, AL, WHI, WLO, STRIDE, KOFF)                       \
    do {                                                                          \
        uint32_t bh[8], bl[8];                                                    \
        ldsm_x4(bh[0], bh[1], bh[2], bh[3],                                       \
                WHI + (uint32_t)((((T0) * 8 + brow) * (STRIDE)) + (KOFF) + bcol) * 2u); \
        ldsm_x4(bh[4], bh[5], bh[6], bh[7],                                       \
                WHI + (uint32_t)(((((T0) + 2) * 8 + brow) * (STRIDE)) + (KOFF) + bcol) * 2u); \
        ldsm_x4(bl[0], bl[1], bl[2], bl[3],                                       \
                WLO + (uint32_t)((((T0) * 8 + brow) * (STRIDE)) + (KOFF) + bcol) * 2u); \
        ldsm_x4(bl[4], bl[5], bl[6], bl[7],                                       \
                WLO + (uint32_t)(((((T0) + 2) * 8 + brow) * (STRIDE)) + (KOFF) + bcol) * 2u); \
        mma_bf16(ACC[(T0) + 0], AH, bh[0], bh[1]);                                \
        mma_bf16(ACC[(T0) + 1], AH, bh[2], bh[3]);                                \
        mma_bf16(ACC[(T0) + 2], AH, bh[4], bh[5]);                                \
        mma_bf16(ACC[(T0) + 3], AH, bh[6], bh[7]);                                \
        mma_bf16(ACC[(T0) + 0], AH, bl[0], bl[1]);                                \
        mma_bf16(ACC[(T0) + 1], AH, bl[2], bl[3]);                                \
        mma_bf16(ACC[(T0) + 2], AH, bl[4], bl[5]);                                \
        mma_bf16(ACC[(T0) + 3], AH, bl[6], bl[7]);                                \
        mma_bf16(ACC[(T0) + 0], AL, bh[0], bh[1]);                                \
        mma_bf16(ACC[(T0) + 1], AL, bh[2], bh[3]);                                \
        mma_bf16(ACC[(T0) + 2], AL, bh[4], bh[5]);                                \
        mma_bf16(ACC[(T0) + 3], AL, bh[6], bh[7]);                                \
    } while (0)

// ---------------------------------------------------------------------------
// Shared memory byte offsets (16B aligned)
// ---------------------------------------------------------------------------
#define SO_WRE_HI 0          // [64][40] bf16  W2T^T
#define SO_WRE_LO 5120
#define SO_WS1_HI 10240      // [64][40] bf16  W2P^T
#define SO_WS1_LO 15360
#define SO_WAT_HI 20480      // [64][72] bf16  W2A^T
#define SO_WAT_LO 29696
#define SO_S1X_HI 38912      // [64][72] bf16  S1 exchange
#define SO_S1X_LO 48128
#define SO_CL     38912      // combine partials (alias S1X; used post-loop)
#define SO_CA     47232      // 32*65 fp32 each
#define SO_RT_HI  57344      // [64][24] bf16  r tile (k padded 16)
#define SO_RT_LO  60416
#define SO_W1T_HI 63488      // [32][24] bf16  BN-folded W1^T
#define SO_W1T_LO 65024
#define SO_VJ     66560      // [64][36] fp32  vj cols 0..31 exchange
#define SO_B1F    75776      // 32 fp32
#define SO_B2F    75904      // 64
#define SO_B1A    76160      // 64
#define SO_QA     76416      // 64
#define SMEM_BYTES 76672

__global__ __launch_bounds__(256, 2) void va_kernel(
    const float* __restrict__ r,
    const float* __restrict__ tpr_w1, const float* __restrict__ tpr_b1,
    const float* __restrict__ bn_g, const float* __restrict__ bn_b,
    const float* __restrict__ bn_m, const float* __restrict__ bn_v,
    const float* __restrict__ tpr_w2, const float* __restrict__ tpr_b2,
    const float* __restrict__ aw2, float* __restrict__ out)
{
    extern __shared__ __align__(16) char sb[];
    __nv_bfloat16* RT_HI  = (__nv_bfloat16*)(sb + SO_RT_HI);
    __nv_bfloat16* RT_LO  = (__nv_bfloat16*)(sb + SO_RT_LO);
    __nv_bfloat16* W1T_HI = (__nv_bfloat16*)(sb + SO_W1T_HI);
    __nv_bfloat16* W1T_LO = (__nv_bfloat16*)(sb + SO_W1T_LO);
    __nv_bfloat16* WRE_HI = (__nv_bfloat16*)(sb + SO_WRE_HI);
    __nv_bfloat16* WRE_LO = (__nv_bfloat16*)(sb + SO_WRE_LO);
    __nv_bfloat16* WS1_HI = (__nv_bfloat16*)(sb + SO_WS1_HI);
    __nv_bfloat16* WS1_LO = (__nv_bfloat16*)(sb + SO_WS1_LO);
    __nv_bfloat16* WAT_HI = (__nv_bfloat16*)(sb + SO_WAT_HI);
    __nv_bfloat16* WAT_LO = (__nv_bfloat16*)(sb + SO_WAT_LO);
    __nv_bfloat16* S1X_HI = (__nv_bfloat16*)(sb + SO_S1X_HI);
    __nv_bfloat16* S1X_LO = (__nv_bfloat16*)(sb + SO_S1X_LO);
    float* CL   = (float*)(sb + SO_CL);
    float* CA   = (float*)(sb + SO_CA);
    float* VJ   = (float*)(sb + SO_VJ);
    float* B1F  = (float*)(sb + SO_B1F);
    float* B2F  = (float*)(sb + SO_B2F);
    float* B1A  = (float*)(sb + SO_B1A);
    float* QA   = (float*)(sb + SO_QA);

    const int tid = threadIdx.x;
    const int wid = tid >> 5, lane = tid & 31;
    const int gid = lane >> 2, tig = lane & 3;
    const int arow = lane & 7, asel = lane >> 3;

    // ---- stage weights ONCE per persistent CTA ----
    for (int idx = tid; idx < 64 * 24; idx += 256) { RT_HI[idx] = __nv_bfloat16(0.f); RT_LO[idx] = __nv_bfloat16(0.f); }
    for (int idx = tid; idx < 32 * 24; idx += 256) { W1T_HI[idx] = __nv_bfloat16(0.f); W1T_LO[idx] = __nv_bfloat16(0.f); }
    if (tid < 32) {
        float sc = bn_g[tid] * rsqrtf(bn_v[tid] + BN_EPS);
        B1F[tid] = (tpr_b1[tid] - bn_m[tid]) * sc + bn_b[tid];
    }
    if (tid < 64) {
        B2F[tid] = tpr_b2[tid];
        B1A[tid] = g_b1a[tid];
    }
    __syncthreads();
    for (int idx = tid; idx < 288; idx += 256) {      // BN-folded W1^T
        const int d = idx >> 5, n = idx & 31;
        const float sc = bn_g[n] * rsqrtf(bn_v[n] + BN_EPS);
        __nv_bfloat16 hi, lo;
        split1(tpr_w1[idx] * sc, hi, lo);
        W1T_HI[n * 24 + d] = hi;
        W1T_LO[n * 24 + d] = lo;
    }
    for (int idx = tid; idx < 2048; idx += 256) {     // W2T^T, W2P^T (stride 40)
        const int n = idx >> 5, k = idx & 31;
        __nv_bfloat16 hi, lo;
        split1(tpr_w2[k * 64 + n], hi, lo);
        WRE_HI[n * 40 + k] = hi; WRE_LO[n * 40 + k] = lo;
        split1(g_w2p[k * 64 + n], hi, lo);
        WS1_HI[n * 40 + k] = hi; WS1_LO[n * 40 + k] = lo;
    }
    for (int idx = tid; idx < 4096; idx += 256) {     // W2A^T (stride 72)
        const int n = idx >> 6, k = idx & 63;
        __nv_bfloat16 hi, lo;
        split1(aw2[k * 64 + n], hi, lo);
        WAT_HI[n * 72 + k] = hi; WAT_LO[n * 72 + k] = lo;
    }

    const int wmod = wid & 3;            // m-tile (warps w and w+4 share it)
    const int nq = wid >> 2;             // n-half owner for Sim phase
    const int m0 = wmod * 16;
    const int r0 = m0 + gid;
    const int brow = arow + (asel >> 1) * 8;
    const int bcol = (asel & 1) * 8;
    const int aoff24 = (m0 + arow + (asel & 1) * 8) * 24 + (asel >> 1) * 8;
    const int aoff72 = (m0 + arow + (asel & 1) * 8) * 72 + (asel >> 1) * 8;

    const uint32_t RThi_a  = (uint32_t)__cvta_generic_to_shared(RT_HI);
    const uint32_t RTlo_a  = (uint32_t)__cvta_generic_to_shared(RT_LO);
    const uint32_t W1Thi_a = (uint32_t)__cvta_generic_to_shared(W1T_HI);
    const uint32_t W1Tlo_a = (uint32_t)__cvta_generic_to_shared(W1T_LO);
    const uint32_t WS1hi_a = (uint32_t)__cvta_generic_to_shared(WS1_HI);
    const uint32_t WS1lo_a = (uint32_t)__cvta_generic_to_shared(WS1_LO);
    const uint32_t WREhi_a = (uint32_t)__cvta_generic_to_shared(WRE_HI);
    const uint32_t WRElo_a = (uint32_t)__cvta_generic_to_shared(WRE_LO);
    const uint32_t WAThi_a = (uint32_t)__cvta_generic_to_shared(WAT_HI) + (uint32_t)(nq * 32 * 72 * 2);
    const uint32_t WATlo_a = (uint32_t)__cvta_generic_to_shared(WAT_LO) + (uint32_t)(nq * 32 * 72 * 2);
    const uint32_t S1Xhi_a = (uint32_t)__cvta_generic_to_shared(S1X_HI);
    const uint32_t S1Xlo_a = (uint32_t)__cvta_generic_to_shared(S1X_LO);

    for (int row = blockIdx.x; row < NROW; row += GRID_PERS) {
        const int b = row >> 8;
        const float* rrow = r + (size_t)row * (TT * 9);

        // ---- stage QA + r tile 0 (prev row's reads all barrier-protected) ----
        if (tid < 64) QA[tid] = g_proj[row * 128 + tid];
        float4 rpre;
        if (tid < 144) rpre = ((const float4*)rrow)[tid];
        if (tid < 144) {
            const int e0 = tid * 4;
#pragma unroll
            for (int u = 0; u < 4; u++) {
                const int e = e0 + u, j = e / 9, d = e - j * 9;
                __nv_bfloat16 hi, lo;
                split1(((const float*)&rpre)[u], hi, lo);
                RT_HI[j * 24 + d] = hi;
                RT_LO[j * 24 + d] = lo;
            }
        }
        __syncthreads();

        float l8[8], a8[8];
#pragma unroll
        for (int s = 0; s < 8; s++) { l8[s] = 0.f; a8[s] = 0.f; }

        for (int jt = 0; jt < 4; jt++) {
            const int j0 = jt * 64;

            // ---- Phase A (regs, every warp): H = relu(r @ W1F + B1F) ----
            uint32_t Hhi[2][4], Hlo[2][4];
            {
                uint32_t rahi[4], ralo[4];
                ldsm_x4(rahi[0], rahi[1], rahi[2], rahi[3], RThi_a + (uint32_t)aoff24 * 2u);
                ldsm_x4(ralo[0], ralo[1], ralo[2], ralo[3], RTlo_a + (uint32_t)aoff24 * 2u);
                // prefetch next r tile while MMAs run
                if (jt < 3 && tid < 144)
                    rpre = ((const float4*)(rrow + (j0 + 64) * 9))[tid];
                float accA[4][4];
#pragma unroll
                for (int t = 0; t < 4; t++)
#pragma unroll
                    for (int u = 0; u < 4; u++) accA[t][u] = 0.f;
                MMA_GROUP4(accA, 0, rahi, ralo, W1Thi_a, W1Tlo_a, 24, 0);
#pragma unroll
                for (int ks = 0; ks < 2; ks++) {
                    const int t0 = 2 * ks, t1 = 2 * ks + 1;
                    const float2 bb0 = *(const float2*)(B1F + t0 * 8 + 2 * tig);
                    const float2 bb1 = *(const float2*)(B1F + t1 * 8 + 2 * tig);
                    split2(fmaxf(accA[t0][0] + bb0.x, 0.f), fmaxf(accA[t0][1] + bb0.y, 0.f),
                           Hhi[ks][0], Hlo[ks][0]);
                    split2(fmaxf(accA[t0][2] + bb0.x, 0.f), fmaxf(accA[t0][3] + bb0.y, 0.f),
                           Hhi[ks][1], Hlo[ks][1]);
                    split2(fmaxf(accA[t1][0] + bb1.x, 0.f), fmaxf(accA[t1][1] + bb1.y, 0.f),
                           Hhi[ks][2], Hlo[ks][2]);
                    split2(fmaxf(accA[t1][2] + bb1.x, 0.f), fmaxf(accA[t1][3] + bb1.y, 0.f),
                           Hhi[ks][3], Hlo[ks][3]);
                }
            }

            float accD[4][4];
#pragma unroll
            for (int t = 0; t < 4; t++)
#pragma unroll
                for (int u = 0; u < 4; u++) accD[t][u] = 0.f;
            float vjk[4][4];                   // warps 4-7: vj cols 32..63

            if (wid < 4) {
                // ---- warps 0-3: S1 = relu(H@W2P + qa - ka + b1a) ----
                float accS[8][4];
#pragma unroll
                for (int t = 0; t < 8; t++)
#pragma unroll
                    for (int u = 0; u < 4; u++) accS[t][u] = 0.f;
#pragma unroll
                for (int g = 0; g < 2; g++)
#pragma unroll
                    for (int ks = 0; ks < 2; ks++)
                        MMA_GROUP4(accS, g * 4, Hhi[ks], Hlo[ks], WS1hi_a, WS1lo_a, 40, ks * 16);
                const float* ka0p = &g_proj[(b * TT + j0 + r0) * 128 + 64];
                const float* ka1p = &g_proj[(b * TT + j0 + r0 + 8) * 128 + 64];
                uint32_t s1hi[4][4], s1lo[4][4];
#pragma unroll
                for (int kg = 0; kg < 4; kg++) {
#pragma unroll
                    for (int half = 0; half < 2; half++) {
                        const int tt = 2 * kg + half;
                        const int c = tt * 8 + 2 * tig;
                        const float2 qa2 = *(const float2*)(QA + c);
                        const float2 ba2 = *(const float2*)(B1A + c);
                        const float2 ka0 = *(const float2*)(ka0p + c);
                        const float2 ka1 = *(const float2*)(ka1p + c);
                        const float s00 = fmaxf(accS[tt][0] + qa2.x - ka0.x + ba2.x, 0.f);
                        const float s01 = fmaxf(accS[tt][1] + qa2.y - ka0.y + ba2.y, 0.f);
                        const float s10 = fmaxf(accS[tt][2] + qa2.x - ka1.x + ba2.x, 0.f);
                        const float s11 = fmaxf(accS[tt][3] + qa2.y - ka1.y + ba2.y, 0.f);
                        uint32_t hi0, lo0, hi1, lo1;
                        split2(s00, s01, hi0, lo0);
                        split2(s10, s11, hi1, lo1);
                        s1hi[kg][half * 2] = hi0;     s1lo[kg][half * 2] = lo0;
                        s1hi[kg][half * 2 + 1] = hi1; s1lo[kg][half * 2 + 1] = lo1;
                        *(uint32_t*)(S1X_HI + r0 * 72 + c) = hi0;
                        *(uint32_t*)(S1X_LO + r0 * 72 + c) = lo0;
                        *(uint32_t*)(S1X_HI + (r0 + 8) * 72 + c) = hi1;
                        *(uint32_t*)(S1X_LO + (r0 + 8) * 72 + c) = lo1;
                    }
                }
                BAR_ARRIVE(1);                 // S1X published
                // Sim immediately from own fragments — no wait on warps 4-7
#pragma unroll
                for (int ks = 0; ks < 4; ks++)
                    MMA_GROUP4(accD, 0, s1hi[ks], s1lo[ks], WAThi_a, WATlo_a, 72, ks * 16);
                BAR_SYNC(2);                   // wait for VJ
            } else {
                // ---- warps 4-7: RE = H@W2T + b2f ; vj = RE + vg ----
                float accR[8][4];
#pragma unroll
                for (int t = 0; t < 8; t++)
#pragma unroll
                    for (int u = 0; u < 4; u++) accR[t][u] = 0.f;
#pragma unroll
                for (int g = 0; g < 2; g++)
#pragma unroll
                    for (int ks = 0; ks < 2; ks++)
                        MMA_GROUP4(accR, g * 4, Hhi[ks], Hlo[ks], WREhi_a, WRElo_a, 40, ks * 16);
                const float* v0p = &g_qkv[(b * TT + j0 + r0) * 192 + 128];
                const float* v1p = &g_qkv[(b * TT + j0 + r0 + 8) * 192 + 128];
#pragma unroll
                for (int tt = 0; tt < 8; tt++) {
                    const int c = tt * 8 + 2 * tig;
                    const float2 bf2 = *(const float2*)(B2F + c);
                    const float2 vg0 = *(const float2*)(v0p + c);
                    const float2 vg1 = *(const float2*)(v1p + c);
                    const float j00 = accR[tt][0] + bf2.x + vg0.x;
                    const float j01 = accR[tt][1] + bf2.y + vg0.y;
                    const float j10 = accR[tt][2] + bf2.x + vg1.x;
                    const float j11 = accR[tt][3] + bf2.y + vg1.y;
                    if (tt < 4) {            // cols 0..31 -> smem for warps 0-3
                        *(float2*)(VJ + r0 * 36 + c) = make_float2(j00, j01);
                        *(float2*)(VJ + (r0 + 8) * 36 + c) = make_float2(j10, j11);
                    } else {                 // cols 32..63 stay local
                        vjk[tt - 4][0] = j00; vjk[tt - 4][1] = j01;
                        vjk[tt - 4][2] = j10; vjk[tt - 4][3] = j11;
                    }
                }
                BAR_ARRIVE(2);                 // VJ published
                BAR_SYNC(1);                   // wait for S1X
                uint32_t s1hi[4][4], s1lo[4][4];
#pragma unroll
                for (int ks = 0; ks < 4; ks++) {
                    ldsm_x4(s1hi[ks][0], s1hi[ks][1], s1hi[ks][2], s1hi[ks][3],
                            S1Xhi_a + (uint32_t)(aoff72 + ks * 16) * 2u);
                    ldsm_x4(s1lo[ks][0], s1lo[ks][1], s1lo[ks][2], s1lo[ks][3],
                            S1Xlo_a + (uint32_t)(aoff72 + ks * 16) * 2u);
                }
#pragma unroll
                for (int ks = 0; ks < 4; ks++)
                    MMA_GROUP4(accD, 0, s1hi[ks], s1lo[ks], WAThi_a, WATlo_a, 72, ks * 16);
            }

            // ---- softmax accumulate in fragment layout ----
#pragma unroll
            for (int tt = 0; tt < 4; tt++) {
                float vj00, vj01, vj10, vj11;
                if (wid < 4) {
                    const int c = tt * 8 + 2 * tig;
                    const float2 a0v = *(const float2*)(VJ + r0 * 36 + c);
                    const float2 a1v = *(const float2*)(VJ + (r0 + 8) * 36 + c);
                    vj00 = a0v.x; vj01 = a0v.y; vj10 = a1v.x; vj11 = a1v.y;
                } else {
                    vj00 = vjk[tt][0]; vj01 = vjk[tt][1];
                    vj10 = vjk[tt][2]; vj11 = vjk[tt][3];
                }
                const float e00 = __expf(accD[tt][0]);
                const float e01 = __expf(accD[tt][1]);
                const float e10 = __expf(accD[tt][2]);
                const float e11 = __expf(accD[tt][3]);
                l8[tt * 2 + 0] += e00 + e10;
                l8[tt * 2 + 1] += e01 + e11;
                a8[tt * 2 + 0] += e00 * vj00 + e10 * vj10;
                a8[tt * 2 + 1] += e01 * vj01 + e11 * vj11;
            }

            // ---- store next r tile (all Phase-A RT reads provably done:
            //      each group's bar.sync waited on the other's post-Phase-A arrive) ----
            if (jt < 3 && tid < 144) {
                const int e0 = tid * 4;
#pragma unroll
                for (int u = 0; u < 4; u++) {
                    const int e = e0 + u, j = e / 9, d = e - j * 9;
                    __nv_bfloat16 hi, lo;
                    split1(((const float*)&rpre)[u], hi, lo);
                    RT_HI[j * 24 + d] = hi;
                    RT_LO[j * 24 + d] = lo;
                }
            }
            __syncthreads();   // guards RT STS vs next ldsm + S1X/VJ reuse
        }

        // ---- cross-warp combine (CL/CA alias S1X space) ----
        {
            const int p = wmod * 8 + gid;
#pragma unroll
            for (int tt = 0; tt < 4; tt++) {
#pragma unroll
                for (int u = 0; u < 2; u++) {
                    const int c = nq * 32 + tt * 8 + 2 * tig + u;
                    CL[p * 65 + c] = l8[tt * 2 + u];
                    CA[p * 65 + c] = a8[tt * 2 + u];
                }
            }
        }
        __syncthreads();
        if (tid < 64) {
            float L = 0.f, A = 0.f;
#pragma unroll
            for (int pp = 0; pp < 32; pp++) {
                L += CL[pp * 65 + tid];
                A += CA[pp * 65 + tid];
            }
            out[row * 64 + tid] = A / L;
        }
        __syncthreads();           // CL/CA reads done before next row's S1X writes
    }
}

// ---------------------------------------------------------------------------
extern "C" void kernel_launch(void* const* d_in, const int* in_sizes, int n_in,
                              void* d_out, int out_size) {
    (void)in_sizes; (void)n_in; (void)out_size;
    const float* x      = (const float*)d_in[0];
    const float* r      = (const float*)d_in[1];
    const float* w_qkv  = (const float*)d_in[2];
    const float* tpr_w1 = (const float*)d_in[3];
    const float* tpr_b1 = (const float*)d_in[4];
    const float* bn_g   = (const float*)d_in[5];
    const float* bn_b   = (const float*)d_in[6];
    const float* bn_m   = (const float*)d_in[7];
    const float* bn_v   = (const float*)d_in[8];
    const float* tpr_w2 = (const float*)d_in[9];
    const float* tpr_b2 = (const float*)d_in[10];
    const float* aw1    = (const float*)d_in[11];
    const float* ab1    = (const float*)d_in[12];
    const float* aw2    = (const float*)d_in[13];
    float* out = (float*)d_out;

    cudaFuncSetAttribute(va_kernel, cudaFuncAttributeMaxDynamicSharedMemorySize,
                         SMEM_BYTES);

    prelude_kernel<<<129, 256>>>(x, w_qkv, aw1, tpr_w2, tpr_b2, ab1);
    va_kernel<<<GRID_PERS, 256, SMEM_BYTES>>>(r, tpr_w1, tpr_b1, bn_g, bn_b, bn_m,
                                              bn_v, tpr_w2, tpr_b2, aw2, out);
}

// round 15
// speedup vs baseline: 1.2171x; 1.0179x over previous
#include <cuda_runtime.h>
#include <cuda_bf16.h>
#include <math.h>
#include <stdint.h>

#define TT 256
#define NROW 2048            // B*T
#define BN_EPS 1e-5f
#define GRID_PERS 296        // 148 SMs x 2 CTAs = one full wave

// scratch
__device__ float g_qkv[NROW * 192];    // only v-part (cols 128..191) is populated/used
__device__ float g_proj[NROW * 128];   // qA|kA per row  ({q,k}@attn_w1)
__device__ float g_w2p[32 * 64];       // tpr_w2 @ attn_w1
__device__ float g_b1a[64];            // tpr_b2 @ attn_w1 + attn_b1

// ---------------------------------------------------------------------------
// Fused prelude: blocks 0..127 -> qkv+proj for 16 rows each; block 128 -> w2p
// ---------------------------------------------------------------------------
__global__ __launch_bounds__(256) void prelude_kernel(
    const float* __restrict__ x, const float* __restrict__ w_qkv,
    const float* __restrict__ aw1, const float* __restrict__ tpr_w2,
    const float* __restrict__ tpr_b2, const float* __restrict__ ab1)
{
    const int tid = threadIdx.x;

    __shared__ float sA[4096];         // aw1 (block 128) | unused others
    __shared__ float xs[16 * 128];     // 16 rows of x    | w2s (block 128, first 2048)
    __shared__ float qs[16 * 192];     // 16 rows of qkv

    if (blockIdx.x == 128) {
        // ---- W2P = tpr_w2 @ attn_w1 ; b1a = tpr_b2 @ attn_w1 + attn_b1 ----
        float* w2s = xs;               // reuse xs region (2048 floats)
        for (int i = tid; i < 2048; i += 256) w2s[i] = tpr_w2[i];
        for (int i = tid; i < 4096; i += 256) sA[i] = aw1[i];
        __syncthreads();
#pragma unroll
        for (int kk = 0; kk < 8; kk++) {
            const int idx = tid + kk * 256;        // 0..2047
            const int h = idx >> 6, c = idx & 63;
            float acc = 0.f;
#pragma unroll 8
            for (int d = 0; d < 64; d++) acc += w2s[h * 64 + d] * sA[d * 64 + c];
            g_w2p[idx] = acc;
        }
        if (tid < 64) {
            float accb = ab1[tid];
#pragma unroll 8
            for (int d = 0; d < 64; d++) accb += tpr_b2[d] * sA[d * 64 + tid];
            g_b1a[tid] = accb;
        }
        return;
    }

    const int r0 = blockIdx.x * 16;

    // stage x rows
    for (int idx = tid; idx < 16 * 128; idx += 256)
        xs[idx] = x[(size_t)r0 * 128 + idx];
    __syncthreads();

    // qkv: 192 cols, w_qkv read ONCE per block
    if (tid < 192) {
        const int col = tid;
        float acc[16];
#pragma unroll
        for (int rr = 0; rr < 16; rr++) acc[rr] = 0.f;
#pragma unroll 8
        for (int d = 0; d < 128; d++) {
            const float wv = w_qkv[d * 192 + col];
#pragma unroll
            for (int rr = 0; rr < 16; rr++)
                acc[rr] += xs[rr * 128 + d] * wv;
        }
#pragma unroll
        for (int rr = 0; rr < 16; rr++) {
            qs[rr * 192 + col] = acc[rr];
            if (col >= 128)                       // only v needed downstream
                g_qkv[(size_t)(r0 + rr) * 192 + col] = acc[rr];
        }
    }
    __syncthreads();

    // proj: qA|kA = {q,k} @ aw1
    {
        const int col = tid & 63;
        const int half = (tid >> 6) & 1;          // 0 = q, 1 = k
        const int rg = tid >> 7;                  // row group (8 rows)
        float acc8[8];
#pragma unroll
        for (int rr = 0; rr < 8; rr++) acc8[rr] = 0.f;
#pragma unroll 8
        for (int d = 0; d < 64; d++) {
            const float av = aw1[d * 64 + col];
#pragma unroll
            for (int rr = 0; rr < 8; rr++)
                acc8[rr] += qs[(rg * 8 + rr) * 192 + half * 64 + d] * av;
        }
#pragma unroll
        for (int rr = 0; rr < 8; rr++)
            g_proj[(size_t)(r0 + rg * 8 + rr) * 128 + half * 64 + col] = acc8[rr];
    }
}

// ---------------------------------------------------------------------------
// helpers
// ---------------------------------------------------------------------------
__device__ __forceinline__ void mma_bf16(float* d, const uint32_t* a,
                                         uint32_t b0, uint32_t b1) {
    asm volatile(
        "mma.sync.aligned.m16n8k16.row.col.f32.bf16.bf16.f32 "
        "{%0,%1,%2,%3}, {%4,%5,%6,%7}, {%8,%9}, {%0,%1,%2,%3};"
        : "+f"(d[0]), "+f"(d[1]), "+f"(d[2]), "+f"(d[3])
        : "r"(a[0]), "r"(a[1]), "r"(a[2]), "r"(a[3]), "r"(b0), "r"(b1));
}

__device__ __forceinline__ void ldsm_x4(uint32_t& r0, uint32_t& r1,
                                        uint32_t& r2, uint32_t& r3, uint32_t addr) {
    asm volatile("ldmatrix.sync.aligned.m8n8.x4.shared.b16 {%0,%1,%2,%3}, [%4];"
                 : "=r"(r0), "=r"(r1), "=r"(r2), "=r"(r3) : "r"(addr));
}

#define BAR_ARRIVE(id) asm volatile("bar.arrive %0, %1;" :: "r"(id), "r"(256) : "memory")
#define BAR_SYNC(id)   asm volatile("bar.sync %0, %1;"   :: "r"(id), "r"(256) : "memory")

__device__ __forceinline__ uint32_t b2u(__nv_bfloat162 v) {
    return *reinterpret_cast<uint32_t*>(&v);
}

__device__ __forceinline__ void split2(float x, float y, uint32_t& hi, uint32_t& lo) {
    __nv_bfloat16 hx = __float2bfloat16_rn(x);
    __nv_bfloat16 hy = __float2bfloat16_rn(y);
    float rx = x - __bfloat162float(hx);
    float ry = y - __bfloat162float(hy);
    __nv_bfloat162 h2; h2.x = hx; h2.y = hy;
    hi = b2u(h2);
    lo = b2u(__floats2bfloat162_rn(rx, ry));
}

__device__ __forceinline__ void split1(float x, __nv_bfloat16& hi, __nv_bfloat16& lo) {
    hi = __float2bfloat16_rn(x);
    lo = __float2bfloat16_rn(x - __bfloat162float(hi));
}

// 4 n-tiles, 3-term bf16x3 split, dependency distance 4 (12 MMAs)
#define MMA_GROUP4(ACC, T0, AH, AL, WHI, WLO, STRIDE, KOFF)                       \
    do {                                                                          \
        uint32_t bh[8], bl[8];                                                    \
        ldsm_x4(bh[0], bh[1], bh[2], bh[3],                                       \
                WHI + (uint32_t)((((T0) * 8 + brow) * (STRIDE)) + (KOFF) + bcol) * 2u); \
        ldsm_x4(bh[4], bh[5], bh[6], bh[7],                                       \
                WHI + (uint32_t)(((((T0) + 2) * 8 + brow) * (STRIDE)) + (KOFF) + bcol) * 2u); \
        ldsm_x4(bl[0], bl[1], bl[2], bl[3],                                       \
                WLO + (uint32_t)((((T0) * 8 + brow) * (STRIDE)) + (KOFF) + bcol) * 2u); \
        ldsm_x4(bl[4], bl[5], bl[6], bl[7],                                       \
                WLO + (uint32_t)(((((T0) + 2) * 8 + brow) * (STRIDE)) + (KOFF) + bcol) * 2u); \
        mma_bf16(ACC[(T0) + 0], AH, bh[0], bh[1]);                                \
        mma_bf16(ACC[(T0) + 1], AH, bh[2], bh[3]);                                \
        mma_bf16(ACC[(T0) + 2], AH, bh[4], bh[5]);                                \
        mma_bf16(ACC[(T0) + 3], AH, bh[6], bh[7]);                                \
        mma_bf16(ACC[(T0) + 0], AH, bl[0], bl[1]);                                \
        mma_bf16(ACC[(T0) + 1], AH, bl[2], bl[3]);                                \
        mma_bf16(ACC[(T0) + 2], AH, bl[4], bl[5]);                                \
        mma_bf16(ACC[(T0) + 3], AH, bl[6], bl[7]);                                \
        mma_bf16(ACC[(T0) + 0], AL, bh[0], bh[1]);                                \
        mma_bf16(ACC[(T0) + 1], AL, bh[2], bh[3]);                                \
        mma_bf16(ACC[(T0) + 2], AL, bh[4], bh[5]);                                \
        mma_bf16(ACC[(T0) + 3], AL, bh[6], bh[7]);                                \
    } while (0)

// ---------------------------------------------------------------------------
// Shared memory byte offsets (16B aligned). S1X / RT / VJ double-buffered.
// ---------------------------------------------------------------------------
#define SO_WRE_HI 0          // [64][40] bf16  W2T^T
#define SO_WRE_LO 5120
#define SO_WS1_HI 10240      // [64][40] bf16  W2P^T
#define SO_WS1_LO 15360
#define SO_WAT_HI 20480      // [64][72] bf16  W2A^T
#define SO_WAT_LO 29696
#define SO_S1X    38912      // [2] x { HI 9216 | LO 9216 } = 36864 (ends 75776)
#define S1X_BUF   18432
#define SO_CL     38912      // combine partials (alias S1X[0]; post-loop only)
#define SO_CA     47232      // 32*65 fp32 each
#define SO_RT     75776      // [2] x { HI 3072 | LO 3072 } = 12288 (ends 88064)
#define RT_BUF    6144
#define SO_W1T_HI 88064      // [32][24] bf16
#define SO_W1T_LO 89600      // ends 91136
#define SO_VJ     91136      // [2] x [64][36] fp32 = 18432 (ends 109568)
#define VJ_BUF    9216
#define SO_B1F    109568     // 32 fp32
#define SO_B2F    109696     // 64
#define SO_B1A    109952     // 64
#define SO_QA     110208     // 64
#define SMEM_BYTES 110464

__global__ __launch_bounds__(256, 2) void va_kernel(
    const float* __restrict__ r,
    const float* __restrict__ tpr_w1, const float* __restrict__ tpr_b1,
    const float* __restrict__ bn_g, const float* __restrict__ bn_b,
    const float* __restrict__ bn_m, const float* __restrict__ bn_v,
    const float* __restrict__ tpr_w2, const float* __restrict__ tpr_b2,
    const float* __restrict__ aw2, float* __restrict__ out)
{
    extern __shared__ __align__(16) char sb[];
    __nv_bfloat16* W1T_HI = (__nv_bfloat16*)(sb + SO_W1T_HI);
    __nv_bfloat16* W1T_LO = (__nv_bfloat16*)(sb + SO_W1T_LO);
    __nv_bfloat16* WRE_HI = (__nv_bfloat16*)(sb + SO_WRE_HI);
    __nv_bfloat16* WRE_LO = (__nv_bfloat16*)(sb + SO_WRE_LO);
    __nv_bfloat16* WS1_HI = (__nv_bfloat16*)(sb + SO_WS1_HI);
    __nv_bfloat16* WS1_LO = (__nv_bfloat16*)(sb + SO_WS1_LO);
    __nv_bfloat16* WAT_HI = (__nv_bfloat16*)(sb + SO_WAT_HI);
    __nv_bfloat16* WAT_LO = (__nv_bfloat16*)(sb + SO_WAT_LO);
    float* CL   = (float*)(sb + SO_CL);
    float* CA   = (float*)(sb + SO_CA);
    float* B1F  = (float*)(sb + SO_B1F);
    float* B2F  = (float*)(sb + SO_B2F);
    float* B1A  = (float*)(sb + SO_B1A);
    float* QA   = (float*)(sb + SO_QA);

    const int tid = threadIdx.x;
    const int wid = tid >> 5, lane = tid & 31;
    const int gid = lane >> 2, tig = lane & 3;
    const int arow = lane & 7, asel = lane >> 3;

    // ---- stage weights ONCE per persistent CTA ----
    // zero both RT buffers (hi+lo, padded cols stay 0): 12288 B = 6144 bf16
    for (int idx = tid; idx < 6144; idx += 256)
        ((__nv_bfloat16*)(sb + SO_RT))[idx] = __nv_bfloat16(0.f);
    for (int idx = tid; idx < 32 * 24; idx += 256) { W1T_HI[idx] = __nv_bfloat16(0.f); W1T_LO[idx] = __nv_bfloat16(0.f); }
    if (tid < 32) {
        float sc = bn_g[tid] * rsqrtf(bn_v[tid] + BN_EPS);
        B1F[tid] = (tpr_b1[tid] - bn_m[tid]) * sc + bn_b[tid];
    }
    if (tid < 64) {
        B2F[tid] = tpr_b2[tid];
        B1A[tid] = g_b1a[tid];
    }
    __syncthreads();
    for (int idx = tid; idx < 288; idx += 256) {      // BN-folded W1^T
        const int d = idx >> 5, n = idx & 31;
        const float sc = bn_g[n] * rsqrtf(bn_v[n] + BN_EPS);
        __nv_bfloat16 hi, lo;
        split1(tpr_w1[idx] * sc, hi, lo);
        W1T_HI[n * 24 + d] = hi;
        W1T_LO[n * 24 + d] = lo;
    }
    for (int idx = tid; idx < 2048; idx += 256) {     // W2T^T, W2P^T (stride 40)
        const int n = idx >> 5, k = idx & 31;
        __nv_bfloat16 hi, lo;
        split1(tpr_w2[k * 64 + n], hi, lo);
        WRE_HI[n * 40 + k] = hi; WRE_LO[n * 40 + k] = lo;
        split1(g_w2p[k * 64 + n], hi, lo);
        WS1_HI[n * 40 + k] = hi; WS1_LO[n * 40 + k] = lo;
    }
    for (int idx = tid; idx < 4096; idx += 256) {     // W2A^T (stride 72)
        const int n = idx >> 6, k = idx & 63;
        __nv_bfloat16 hi, lo;
        split1(aw2[k * 64 + n], hi, lo);
        WAT_HI[n * 72 + k] = hi; WAT_LO[n * 72 + k] = lo;
    }

    const int wmod = wid & 3;            // m-tile (warps w and w+4 share it)
    const int nq = wid >> 2;             // n-half owner for Sim phase
    const int m0 = wmod * 16;
    const int r0 = m0 + gid;
    const int brow = arow + (asel >> 1) * 8;
    const int bcol = (asel & 1) * 8;
    const int aoff24 = (m0 + arow + (asel & 1) * 8) * 24 + (asel >> 1) * 8;
    const int aoff72 = (m0 + arow + (asel & 1) * 8) * 72 + (asel >> 1) * 8;

    const uint32_t RT_a    = (uint32_t)__cvta_generic_to_shared(sb + SO_RT);
    const uint32_t S1X_a   = (uint32_t)__cvta_generic_to_shared(sb + SO_S1X);
    const uint32_t W1Thi_a = (uint32_t)__cvta_generic_to_shared(W1T_HI);
    const uint32_t W1Tlo_a = (uint32_t)__cvta_generic_to_shared(W1T_LO);
    const uint32_t WS1hi_a = (uint32_t)__cvta_generic_to_shared(WS1_HI);
    const uint32_t WS1lo_a = (uint32_t)__cvta_generic_to_shared(WS1_LO);
    const uint32_t WREhi_a = (uint32_t)__cvta_generic_to_shared(WRE_HI);
    const uint32_t WRElo_a = (uint32_t)__cvta_generic_to_shared(WRE_LO);
    const uint32_t WAThi_a = (uint32_t)__cvta_generic_to_shared(WAT_HI) + (uint32_t)(nq * 32 * 72 * 2);
    const uint32_t WATlo_a = (uint32_t)__cvta_generic_to_shared(WAT_LO) + (uint32_t)(nq * 32 * 72 * 2);

    for (int row = blockIdx.x; row < NROW; row += GRID_PERS) {
        const int b = row >> 8;
        const float* rrow = r + (size_t)row * (TT * 9);

        // ---- stage QA + r tile 0 -> RT[0]; prefetch tile 1 ----
        if (tid < 64) QA[tid] = g_proj[row * 128 + tid];
        float4 rpre;
        if (tid < 144) {
            rpre = ((const float4*)rrow)[tid];
            __nv_bfloat16* RT0_HI = (__nv_bfloat16*)(sb + SO_RT);
            __nv_bfloat16* RT0_LO = RT0_HI + 1536;
            const int e0 = tid * 4;
#pragma unroll
            for (int u = 0; u < 4; u++) {
                const int e = e0 + u, j = e / 9, d = e - j * 9;
                __nv_bfloat16 hi, lo;
                split1(((const float*)&rpre)[u], hi, lo);
                RT0_HI[j * 24 + d] = hi;
                RT0_LO[j * 24 + d] = lo;
            }
            rpre = ((const float4*)(rrow + 576))[tid];   // tile 1
        }
        __syncthreads();

        float l8[8], a8[8];
#pragma unroll
        for (int s = 0; s < 8; s++) { l8[s] = 0.f; a8[s] = 0.f; }

        for (int jt = 0; jt < 4; jt++) {
            const int j0 = jt * 64;
            const int p = jt & 1;
            const uint32_t rt_rd  = RT_a + (uint32_t)(p * RT_BUF);
            const uint32_t s1x_hi = S1X_a + (uint32_t)(p * S1X_BUF);
            const uint32_t s1x_lo = s1x_hi + 9216u;
            __nv_bfloat16* S1Xw_HI = (__nv_bfloat16*)(sb + SO_S1X + p * S1X_BUF);
            __nv_bfloat16* S1Xw_LO = S1Xw_HI + 4608;
            float* VJp = (float*)(sb + SO_VJ + p * VJ_BUF);

            // ---- Phase A (regs, every warp): H = relu(r @ W1F + B1F) ----
            uint32_t Hhi[2][4], Hlo[2][4];
            {
                uint32_t rahi[4], ralo[4];
                ldsm_x4(rahi[0], rahi[1], rahi[2], rahi[3], rt_rd + (uint32_t)aoff24 * 2u);
                ldsm_x4(ralo[0], ralo[1], ralo[2], ralo[3], rt_rd + 3072u + (uint32_t)aoff24 * 2u);
                float accA[4][4];
#pragma unroll
                for (int t = 0; t < 4; t++)
#pragma unroll
                    for (int u = 0; u < 4; u++) accA[t][u] = 0.f;
                MMA_GROUP4(accA, 0, rahi, ralo, W1Thi_a, W1Tlo_a, 24, 0);
#pragma unroll
                for (int ks = 0; ks < 2; ks++) {
                    const int t0 = 2 * ks, t1 = 2 * ks + 1;
                    const float2 bb0 = *(const float2*)(B1F + t0 * 8 + 2 * tig);
                    const float2 bb1 = *(const float2*)(B1F + t1 * 8 + 2 * tig);
                    split2(fmaxf(accA[t0][0] + bb0.x, 0.f), fmaxf(accA[t0][1] + bb0.y, 0.f),
                           Hhi[ks][0], Hlo[ks][0]);
                    split2(fmaxf(accA[t0][2] + bb0.x, 0.f), fmaxf(accA[t0][3] + bb0.y, 0.f),
                           Hhi[ks][1], Hlo[ks][1]);
                    split2(fmaxf(accA[t1][0] + bb1.x, 0.f), fmaxf(accA[t1][1] + bb1.y, 0.f),
                           Hhi[ks][2], Hlo[ks][2]);
                    split2(fmaxf(accA[t1][2] + bb1.x, 0.f), fmaxf(accA[t1][3] + bb1.y, 0.f),
                           Hhi[ks][3], Hlo[ks][3]);
                }
            }

            // ---- store next r tile into RT[p^1] BEFORE arrives (ordering:
            //      all tile-jt RT[p] ldsm reads precede each warp's arrive;
            //      readers of RT[p^1] at jt+1 sit behind this tile's bar.sync) ----
            if (jt < 3 && tid < 144) {
                __nv_bfloat16* RTw_HI = (__nv_bfloat16*)(sb + SO_RT + (p ^ 1) * RT_BUF);
                __nv_bfloat16* RTw_LO = RTw_HI + 1536;
                const int e0 = tid * 4;
#pragma unroll
                for (int u = 0; u < 4; u++) {
                    const int e = e0 + u, j = e / 9, d = e - j * 9;
                    __nv_bfloat16 hi, lo;
                    split1(((const float*)&rpre)[u], hi, lo);
                    RTw_HI[j * 24 + d] = hi;
                    RTw_LO[j * 24 + d] = lo;
                }
                if (jt < 2)
                    rpre = ((const float4*)(rrow + (j0 + 128) * 9))[tid];  // tile jt+2
            }

            float accD[4][4];
#pragma unroll
            for (int t = 0; t < 4; t++)
#pragma unroll
                for (int u = 0; u < 4; u++) accD[t][u] = 0.f;
            float vjk[4][4];                   // warps 4-7: vj cols 32..63

            if (wid < 4) {
                // ---- warps 0-3: S1 = relu(H@W2P + qa - ka + b1a) ----
                float accS[8][4];
#pragma unroll
                for (int t = 0; t < 8; t++)
#pragma unroll
                    for (int u = 0; u < 4; u++) accS[t][u] = 0.f;
#pragma unroll
                for (int g = 0; g < 2; g++)
#pragma unroll
                    for (int ks = 0; ks < 2; ks++)
                        MMA_GROUP4(accS, g * 4, Hhi[ks], Hlo[ks], WS1hi_a, WS1lo_a, 40, ks * 16);
                const float* ka0p = &g_proj[(b * TT + j0 + r0) * 128 + 64];
                const float* ka1p = &g_proj[(b * TT + j0 + r0 + 8) * 128 + 64];
                uint32_t s1hi[4][4], s1lo[4][4];
#pragma unroll
                for (int kg = 0; kg < 4; kg++) {
#pragma unroll
                    for (int half = 0; half < 2; half++) {
                        const int tt = 2 * kg + half;
                        const int c = tt * 8 + 2 * tig;
                        const float2 qa2 = *(const float2*)(QA + c);
                        const float2 ba2 = *(const float2*)(B1A + c);
                        const float2 ka0 = *(const float2*)(ka0p + c);
                        const float2 ka1 = *(const float2*)(ka1p + c);
                        const float s00 = fmaxf(accS[tt][0] + qa2.x - ka0.x + ba2.x, 0.f);
                        const float s01 = fmaxf(accS[tt][1] + qa2.y - ka0.y + ba2.y, 0.f);
                        const float s10 = fmaxf(accS[tt][2] + qa2.x - ka1.x + ba2.x, 0.f);
                        const float s11 = fmaxf(accS[tt][3] + qa2.y - ka1.y + ba2.y, 0.f);
                        uint32_t hi0, lo0, hi1, lo1;
                        split2(s00, s01, hi0, lo0);
                        split2(s10, s11, hi1, lo1);
                        s1hi[kg][half * 2] = hi0;     s1lo[kg][half * 2] = lo0;
                        s1hi[kg][half * 2 + 1] = hi1; s1lo[kg][half * 2 + 1] = lo1;
                        *(uint32_t*)(S1Xw_HI + r0 * 72 + c) = hi0;
                        *(uint32_t*)(S1Xw_LO + r0 * 72 + c) = lo0;
                        *(uint32_t*)(S1Xw_HI + (r0 + 8) * 72 + c) = hi1;
                        *(uint32_t*)(S1Xw_LO + (r0 + 8) * 72 + c) = lo1;
                    }
                }
                BAR_ARRIVE(1);                 // S1X[p] published
#pragma unroll
                for (int ks = 0; ks < 4; ks++)
                    MMA_GROUP4(accD, 0, s1hi[ks], s1lo[ks], WAThi_a, WATlo_a, 72, ks * 16);
                BAR_SYNC(2);                   // wait for VJ[p]
            } else {
                // ---- warps 4-7: RE = H@W2T + b2f ; vj = RE + vg ----
                float accR[8][4];
#pragma unroll
                for (int t = 0; t < 8; t++)
#pragma unroll
                    for (int u = 0; u < 4; u++) accR[t][u] = 0.f;
#pragma unroll
                for (int g = 0; g < 2; g++)
#pragma unroll
                    for (int ks = 0; ks < 2; ks++)
                        MMA_GROUP4(accR, g * 4, Hhi[ks], Hlo[ks], WREhi_a, WRElo_a, 40, ks * 16);
                const float* v0p = &g_qkv[(b * TT + j0 + r0) * 192 + 128];
                const float* v1p = &g_qkv[(b * TT + j0 + r0 + 8) * 192 + 128];
#pragma unroll
                for (int tt = 0; tt < 8; tt++) {
                    const int c = tt * 8 + 2 * tig;
                    const float2 bf2 = *(const float2*)(B2F + c);
                    const float2 vg0 = *(const float2*)(v0p + c);
                    const float2 vg1 = *(const float2*)(v1p + c);
                    const float j00 = accR[tt][0] + bf2.x + vg0.x;
                    const float j01 = accR[tt][1] + bf2.y + vg0.y;
                    const float j10 = accR[tt][2] + bf2.x + vg1.x;
                    const float j11 = accR[tt][3] + bf2.y + vg1.y;
                    if (tt < 4) {            // cols 0..31 -> smem for warps 0-3
                        *(float2*)(VJp + r0 * 36 + c) = make_float2(j00, j01);
                        *(float2*)(VJp + (r0 + 8) * 36 + c) = make_float2(j10, j11);
                    } else {                 // cols 32..63 stay local
                        vjk[tt - 4][0] = j00; vjk[tt - 4][1] = j01;
                        vjk[tt - 4][2] = j10; vjk[tt - 4][3] = j11;
                    }
                }
                BAR_ARRIVE(2);                 // VJ[p] published
                BAR_SYNC(1);                   // wait for S1X[p]
                uint32_t s1hi[4][4], s1lo[4][4];
#pragma unroll
                for (int ks = 0; ks < 4; ks++) {
                    ldsm_x4(s1hi[ks][0], s1hi[ks][1], s1hi[ks][2], s1hi[ks][3],
                            s1x_hi + (uint32_t)(aoff72 + ks * 16) * 2u);
                    ldsm_x4(s1lo[ks][0], s1lo[ks][1], s1lo[ks][2], s1lo[ks][3],
                            s1x_lo + (uint32_t)(aoff72 + ks * 16) * 2u);
                }
#pragma unroll
                for (int ks = 0; ks < 4; ks++)
                    MMA_GROUP4(accD, 0, s1hi[ks], s1lo[ks], WAThi_a, WATlo_a, 72, ks * 16);
            }

            // ---- softmax accumulate in fragment layout (no barrier) ----
#pragma unroll
            for (int tt = 0; tt < 4; tt++) {
                float vj00, vj01, vj10, vj11;
                if (wid < 4) {
                    const int c = tt * 8 + 2 * tig;
                    const float2 a0v = *(const float2*)(VJp + r0 * 36 + c);
                    const float2 a1v = *(const float2*)(VJp + (r0 + 8) * 36 + c);
                    vj00 = a0v.x; vj01 = a0v.y; vj10 = a1v.x; vj11 = a1v.y;
                } else {
                    vj00 = vjk[tt][0]; vj01 = vjk[tt][1];
                    vj10 = vjk[tt][2]; vj11 = vjk[tt][3];
                }
                const float e00 = __expf(accD[tt][0]);
                const float e01 = __expf(accD[tt][1]);
                const float e10 = __expf(accD[tt][2]);
                const float e11 = __expf(accD[tt][3]);
                l8[tt * 2 + 0] += e00 + e10;
                l8[tt * 2 + 1] += e01 + e11;
                a8[tt * 2 + 0] += e00 * vj00 + e10 * vj10;
                a8[tt * 2 + 1] += e01 * vj01 + e11 * vj11;
            }
            // no trailing barrier: all cross-tile hazards are buffer-separated
        }

        // ---- cross-warp combine (CL/CA alias S1X[0] space) ----
        __syncthreads();           // all tile reads (S1X/VJ/RT) complete
        {
            const int p = wmod * 8 + gid;
#pragma unroll
            for (int tt = 0; tt < 4; tt++) {
#pragma unroll
                for (int u = 0; u < 2; u++) {
                    const int c = nq * 32 + tt * 8 + 2 * tig + u;
                    CL[p * 65 + c] = l8[tt * 2 + u];
                    CA[p * 65 + c] = a8[tt * 2 + u];
                }
            }
        }
        __syncthreads();
        if (tid < 64) {
            float L = 0.f, A = 0.f;
#pragma unroll
            for (int pp = 0; pp < 32; pp++) {
                L += CL[pp * 65 + tid];
                A += CA[pp * 65 + tid];
            }
            out[row * 64 + tid] = A / L;
        }
        __syncthreads();           // CL/CA reads done before next row's writes
    }
}

// ---------------------------------------------------------------------------
extern "C" void kernel_launch(void* const* d_in, const int* in_sizes, int n_in,
                              void* d_out, int out_size) {
    (void)in_sizes; (void)n_in; (void)out_size;
    const float* x      = (const float*)d_in[0];
    const float* r      = (const float*)d_in[1];
    const float* w_qkv  = (const float*)d_in[2];
    const float* tpr_w1 = (const float*)d_in[3];
    const float* tpr_b1 = (const float*)d_in[4];
    const float* bn_g   = (const float*)d_in[5];
    const float* bn_b   = (const float*)d_in[6];
    const float* bn_m   = (const float*)d_in[7];
    const float* bn_v   = (const float*)d_in[8];
    const float* tpr_w2 = (const float*)d_in[9];
    const float* tpr_b2 = (const float*)d_in[10];
    const float* aw1    = (const float*)d_in[11];
    const float* ab1    = (const float*)d_in[12];
    const float* aw2    = (const float*)d_in[13];
    float* out = (float*)d_out;

    cudaFuncSetAttribute(va_kernel, cudaFuncAttributeMaxDynamicSharedMemorySize,
                         SMEM_BYTES);

    prelude_kernel<<<129, 256>>>(x, w_qkv, aw1, tpr_w2, tpr_b2, ab1);
    va_kernel<<<GRID_PERS, 256, SMEM_BYTES>>>(r, tpr_w1, tpr_b1, bn_g, bn_b, bn_m,
                                              bn_v, tpr_w2, tpr_b2, aw2, out);
}

// round 16
// speedup vs baseline: 1.2855x; 1.0562x over previous
#include <cuda_runtime.h>
#include <cuda_bf16.h>
#include <math.h>
#include <stdint.h>

#define TT 256
#define NROW 2048            // B*T
#define BN_EPS 1e-5f
#define GRID_PERS 296        // 148 SMs x 2 CTAs = one full wave

// scratch
__device__ float g_qkv[NROW * 192];    // only v-part (cols 128..191) is populated/used
__device__ float g_proj[NROW * 128];   // qA|kA per row  ({q,k}@attn_w1)
__device__ float g_w2p[32 * 64];       // tpr_w2 @ attn_w1
__device__ float g_b1a[64];            // tpr_b2 @ attn_w1 + attn_b1

// ---------------------------------------------------------------------------
// Fused prelude: blocks 0..127 -> qkv+proj for 16 rows each; block 128 -> w2p
// ---------------------------------------------------------------------------
__global__ __launch_bounds__(256) void prelude_kernel(
    const float* __restrict__ x, const float* __restrict__ w_qkv,
    const float* __restrict__ aw1, const float* __restrict__ tpr_w2,
    const float* __restrict__ tpr_b2, const float* __restrict__ ab1)
{
    const int tid = threadIdx.x;

    __shared__ float sA[4096];         // aw1 (block 128) | unused others
    __shared__ float xs[16 * 128];     // 16 rows of x    | w2s (block 128, first 2048)
    __shared__ float qs[16 * 192];     // 16 rows of qkv

    if (blockIdx.x == 128) {
        // ---- W2P = tpr_w2 @ attn_w1 ; b1a = tpr_b2 @ attn_w1 + attn_b1 ----
        float* w2s = xs;               // reuse xs region (2048 floats)
        for (int i = tid; i < 2048; i += 256) w2s[i] = tpr_w2[i];
        for (int i = tid; i < 4096; i += 256) sA[i] = aw1[i];
        __syncthreads();
#pragma unroll
        for (int kk = 0; kk < 8; kk++) {
            const int idx = tid + kk * 256;        // 0..2047
            const int h = idx >> 6, c = idx & 63;
            float acc = 0.f;
#pragma unroll 8
            for (int d = 0; d < 64; d++) acc += w2s[h * 64 + d] * sA[d * 64 + c];
            g_w2p[idx] = acc;
        }
        if (tid < 64) {
            float accb = ab1[tid];
#pragma unroll 8
            for (int d = 0; d < 64; d++) accb += tpr_b2[d] * sA[d * 64 + tid];
            g_b1a[tid] = accb;
        }
        return;
    }

    const int r0 = blockIdx.x * 16;

    // stage x rows
    for (int idx = tid; idx < 16 * 128; idx += 256)
        xs[idx] = x[(size_t)r0 * 128 + idx];
    __syncthreads();

    // qkv: 192 cols, w_qkv read ONCE per block
    if (tid < 192) {
        const int col = tid;
        float acc[16];
#pragma unroll
        for (int rr = 0; rr < 16; rr++) acc[rr] = 0.f;
#pragma unroll 8
        for (int d = 0; d < 128; d++) {
            const float wv = w_qkv[d * 192 + col];
#pragma unroll
            for (int rr = 0; rr < 16; rr++)
                acc[rr] += xs[rr * 128 + d] * wv;
        }
#pragma unroll
        for (int rr = 0; rr < 16; rr++) {
            qs[rr * 192 + col] = acc[rr];
            if (col >= 128)                       // only v needed downstream
                g_qkv[(size_t)(r0 + rr) * 192 + col] = acc[rr];
        }
    }
    __syncthreads();

    // proj: qA|kA = {q,k} @ aw1
    {
        const int col = tid & 63;
        const int half = (tid >> 6) & 1;          // 0 = q, 1 = k
        const int rg = tid >> 7;                  // row group (8 rows)
        float acc8[8];
#pragma unroll
        for (int rr = 0; rr < 8; rr++) acc8[rr] = 0.f;
#pragma unroll 8
        for (int d = 0; d < 64; d++) {
            const float av = aw1[d * 64 + col];
#pragma unroll
            for (int rr = 0; rr < 8; rr++)
                acc8[rr] += qs[(rg * 8 + rr) * 192 + half * 64 + d] * av;
        }
#pragma unroll
        for (int rr = 0; rr < 8; rr++)
            g_proj[(size_t)(r0 + rg * 8 + rr) * 128 + half * 64 + col] = acc8[rr];
    }
}

// ---------------------------------------------------------------------------
// helpers
// ---------------------------------------------------------------------------
__device__ __forceinline__ void mma_bf16(float* d, const uint32_t* a,
                                         uint32_t b0, uint32_t b1) {
    asm volatile(
        "mma.sync.aligned.m16n8k16.row.col.f32.bf16.bf16.f32 "
        "{%0,%1,%2,%3}, {%4,%5,%6,%7}, {%8,%9}, {%0,%1,%2,%3};"
        : "+f"(d[0]), "+f"(d[1]), "+f"(d[2]), "+f"(d[3])
        : "r"(a[0]), "r"(a[1]), "r"(a[2]), "r"(a[3]), "r"(b0), "r"(b1));
}

__device__ __forceinline__ void ldsm_x4(uint32_t& r0, uint32_t& r1,
                                        uint32_t& r2, uint32_t& r3, uint32_t addr) {
    asm volatile("ldmatrix.sync.aligned.m8n8.x4.shared.b16 {%0,%1,%2,%3}, [%4];"
                 : "=r"(r0), "=r"(r1), "=r"(r2), "=r"(r3) : "r"(addr));
}

#define BAR_ARRIVE(id) asm volatile("bar.arrive %0, %1;" :: "r"(id), "r"(256) : "memory")
#define BAR_SYNC(id)   asm volatile("bar.sync %0, %1;"   :: "r"(id), "r"(256) : "memory")

__device__ __forceinline__ uint32_t b2u(__nv_bfloat162 v) {
    return *reinterpret_cast<uint32_t*>(&v);
}

__device__ __forceinline__ void split2(float x, float y, uint32_t& hi, uint32_t& lo) {
    __nv_bfloat16 hx = __float2bfloat16_rn(x);
    __nv_bfloat16 hy = __float2bfloat16_rn(y);
    float rx = x - __bfloat162float(hx);
    float ry = y - __bfloat162float(hy);
    __nv_bfloat162 h2; h2.x = hx; h2.y = hy;
    hi = b2u(h2);
    lo = b2u(__floats2bfloat162_rn(rx, ry));
}

__device__ __forceinline__ void split1(float x, __nv_bfloat16& hi, __nv_bfloat16& lo) {
    hi = __float2bfloat16_rn(x);
    lo = __float2bfloat16_rn(x - __bfloat162float(hi));
}

// 4 n-tiles, 3-term bf16x3 split, dependency distance 4 (12 MMAs)
#define MMA_GROUP4(ACC, T0, AH, AL, WHI, WLO, STRIDE, KOFF)                       \
    do {                                                                          \
        uint32_t bh[8], bl[8];                                                    \
        ldsm_x4(bh[0], bh[1], bh[2], bh[3],                                       \
                WHI + (uint32_t)((((T0) * 8 + brow) * (STRIDE)) + (KOFF) + bcol) * 2u); \
        ldsm_x4(bh[4], bh[5], bh[6], bh[7],                                       \
                WHI + (uint32_t)(((((T0) + 2) * 8 + brow) * (STRIDE)) + (KOFF) + bcol) * 2u); \
        ldsm_x4(bl[0], bl[1], bl[2], bl[3],                                       \
                WLO + (uint32_t)((((T0) * 8 + brow) * (STRIDE)) + (KOFF) + bcol) * 2u); \
        ldsm_x4(bl[4], bl[5], bl[6], bl[7],                                       \
                WLO + (uint32_t)(((((T0) + 2) * 8 + brow) * (STRIDE)) + (KOFF) + bcol) * 2u); \
        mma_bf16(ACC[(T0) + 0], AH, bh[0], bh[1]);                                \
        mma_bf16(ACC[(T0) + 1], AH, bh[2], bh[3]);                                \
        mma_bf16(ACC[(T0) + 2], AH, bh[4], bh[5]);                                \
        mma_bf16(ACC[(T0) + 3], AH, bh[6], bh[7]);                                \
        mma_bf16(ACC[(T0) + 0], AH, bl[0], bl[1]);                                \
        mma_bf16(ACC[(T0) + 1], AH, bl[2], bl[3]);                                \
        mma_bf16(ACC[(T0) + 2], AH, bl[4], bl[5]);                                \
        mma_bf16(ACC[(T0) + 3], AH, bl[6], bl[7]);                                \
        mma_bf16(ACC[(T0) + 0], AL, bh[0], bh[1]);                                \
        mma_bf16(ACC[(T0) + 1], AL, bh[2], bh[3]);                                \
        mma_bf16(ACC[(T0) + 2], AL, bh[4], bh[5]);                                \
        mma_bf16(ACC[(T0) + 3], AL, bh[6], bh[7]);                                \
    } while (0)

// 4 n-tiles, 2-term split (A split, weight hi only): 4 ldsm, 8 MMAs.
// Used ONLY for the Sim GEMM (error budget analysis: |sim| small, exp() cares
// about absolute error; dropped term ~2^-9 relative of sim).
#define MMA_GROUP4_2T(ACC, T0, AH, AL, WHI, STRIDE, KOFF)                         \
    do {                                                                          \
        uint32_t bh[8];                                                           \
        ldsm_x4(bh[0], bh[1], bh[2], bh[3],                                       \
                WHI + (uint32_t)((((T0) * 8 + brow) * (STRIDE)) + (KOFF) + bcol) * 2u); \
        ldsm_x4(bh[4], bh[5], bh[6], bh[7],                                       \
                WHI + (uint32_t)(((((T0) + 2) * 8 + brow) * (STRIDE)) + (KOFF) + bcol) * 2u); \
        mma_bf16(ACC[(T0) + 0], AH, bh[0], bh[1]);                                \
        mma_bf16(ACC[(T0) + 1], AH, bh[2], bh[3]);                                \
        mma_bf16(ACC[(T0) + 2], AH, bh[4], bh[5]);                                \
        mma_bf16(ACC[(T0) + 3], AH, bh[6], bh[7]);                                \
        mma_bf16(ACC[(T0) + 0], AL, bh[0], bh[1]);                                \
        mma_bf16(ACC[(T0) + 1], AL, bh[2], bh[3]);                                \
        mma_bf16(ACC[(T0) + 2], AL, bh[4], bh[5]);                                \
        mma_bf16(ACC[(T0) + 3], AL, bh[6], bh[7]);                                \
    } while (0)

// ---------------------------------------------------------------------------
// Shared memory byte offsets (16B aligned). S1X / RT / VJ double-buffered.
// (WAT_LO region retained in layout but unused — Sim is 2-term.)
// ---------------------------------------------------------------------------
#define SO_WRE_HI 0          // [64][40] bf16  W2T^T
#define SO_WRE_LO 5120
#define SO_WS1_HI 10240      // [64][40] bf16  W2P^T
#define SO_WS1_LO 15360
#define SO_WAT_HI 20480      // [64][72] bf16  W2A^T
#define SO_WAT_LO 29696      // unused
#define SO_S1X    38912      // [2] x { HI 9216 | LO 9216 } = 36864 (ends 75776)
#define S1X_BUF   18432
#define SO_CL     38912      // combine partials (alias S1X[0]; post-loop only)
#define SO_CA     47232      // 32*65 fp32 each
#define SO_RT     75776      // [2] x { HI 3072 | LO 3072 } = 12288 (ends 88064)
#define RT_BUF    6144
#define SO_W1T_HI 88064      // [32][24] bf16
#define SO_W1T_LO 89600      // ends 91136
#define SO_VJ     91136      // [2] x [64][36] fp32 = 18432 (ends 109568)
#define VJ_BUF    9216
#define SO_B1F    109568     // 32 fp32
#define SO_B2F    109696     // 64
#define SO_B1A    109952     // 64
#define SO_QA     110208     // 64
#define SMEM_BYTES 110464

__global__ __launch_bounds__(256, 2) void va_kernel(
    const float* __restrict__ r,
    const float* __restrict__ tpr_w1, const float* __restrict__ tpr_b1,
    const float* __restrict__ bn_g, const float* __restrict__ bn_b,
    const float* __restrict__ bn_m, const float* __restrict__ bn_v,
    const float* __restrict__ tpr_w2, const float* __restrict__ tpr_b2,
    const float* __restrict__ aw2, float* __restrict__ out)
{
    extern __shared__ __align__(16) char sb[];
    __nv_bfloat16* W1T_HI = (__nv_bfloat16*)(sb + SO_W1T_HI);
    __nv_bfloat16* W1T_LO = (__nv_bfloat16*)(sb + SO_W1T_LO);
    __nv_bfloat16* WRE_HI = (__nv_bfloat16*)(sb + SO_WRE_HI);
    __nv_bfloat16* WRE_LO = (__nv_bfloat16*)(sb + SO_WRE_LO);
    __nv_bfloat16* WS1_HI = (__nv_bfloat16*)(sb + SO_WS1_HI);
    __nv_bfloat16* WS1_LO = (__nv_bfloat16*)(sb + SO_WS1_LO);
    __nv_bfloat16* WAT_HI = (__nv_bfloat16*)(sb + SO_WAT_HI);
    float* CL   = (float*)(sb + SO_CL);
    float* CA   = (float*)(sb + SO_CA);
    float* B1F  = (float*)(sb + SO_B1F);
    float* B2F  = (float*)(sb + SO_B2F);
    float* B1A  = (float*)(sb + SO_B1A);
    float* QA   = (float*)(sb + SO_QA);

    const int tid = threadIdx.x;
    const int wid = tid >> 5, lane = tid & 31;
    const int gid = lane >> 2, tig = lane & 3;
    const int arow = lane & 7, asel = lane >> 3;

    // ---- stage weights ONCE per persistent CTA ----
    for (int idx = tid; idx < 6144; idx += 256)
        ((__nv_bfloat16*)(sb + SO_RT))[idx] = __nv_bfloat16(0.f);
    for (int idx = tid; idx < 32 * 24; idx += 256) { W1T_HI[idx] = __nv_bfloat16(0.f); W1T_LO[idx] = __nv_bfloat16(0.f); }
    if (tid < 32) {
        float sc = bn_g[tid] * rsqrtf(bn_v[tid] + BN_EPS);
        B1F[tid] = (tpr_b1[tid] - bn_m[tid]) * sc + bn_b[tid];
    }
    if (tid < 64) {
        B2F[tid] = tpr_b2[tid];
        B1A[tid] = g_b1a[tid];
    }
    __syncthreads();
    for (int idx = tid; idx < 288; idx += 256) {      // BN-folded W1^T
        const int d = idx >> 5, n = idx & 31;
        const float sc = bn_g[n] * rsqrtf(bn_v[n] + BN_EPS);
        __nv_bfloat16 hi, lo;
        split1(tpr_w1[idx] * sc, hi, lo);
        W1T_HI[n * 24 + d] = hi;
        W1T_LO[n * 24 + d] = lo;
    }
    for (int idx = tid; idx < 2048; idx += 256) {     // W2T^T, W2P^T (stride 40)
        const int n = idx >> 5, k = idx & 31;
        __nv_bfloat16 hi, lo;
        split1(tpr_w2[k * 64 + n], hi, lo);
        WRE_HI[n * 40 + k] = hi; WRE_LO[n * 40 + k] = lo;
        split1(g_w2p[k * 64 + n], hi, lo);
        WS1_HI[n * 40 + k] = hi; WS1_LO[n * 40 + k] = lo;
    }
    for (int idx = tid; idx < 4096; idx += 256) {     // W2A^T hi only (stride 72)
        const int n = idx >> 6, k = idx & 63;
        WAT_HI[n * 72 + k] = __float2bfloat16_rn(aw2[k * 64 + n]);
    }

    const int wmod = wid & 3;            // m-tile (warps w and w+4 share it)
    const int nq = wid >> 2;             // n-half owner for Sim phase
    const int m0 = wmod * 16;
    const int r0 = m0 + gid;
    const int brow = arow + (asel >> 1) * 8;
    const int bcol = (asel & 1) * 8;
    const int aoff24 = (m0 + arow + (asel & 1) * 8) * 24 + (asel >> 1) * 8;
    const int aoff72 = (m0 + arow + (asel & 1) * 8) * 72 + (asel >> 1) * 8;

    const uint32_t RT_a    = (uint32_t)__cvta_generic_to_shared(sb + SO_RT);
    const uint32_t S1X_a   = (uint32_t)__cvta_generic_to_shared(sb + SO_S1X);
    const uint32_t W1Thi_a = (uint32_t)__cvta_generic_to_shared(W1T_HI);
    const uint32_t W1Tlo_a = (uint32_t)__cvta_generic_to_shared(W1T_LO);
    const uint32_t WS1hi_a = (uint32_t)__cvta_generic_to_shared(WS1_HI);
    const uint32_t WS1lo_a = (uint32_t)__cvta_generic_to_shared(WS1_LO);
    const uint32_t WREhi_a = (uint32_t)__cvta_generic_to_shared(WRE_HI);
    const uint32_t WRElo_a = (uint32_t)__cvta_generic_to_shared(WRE_LO);
    const uint32_t WAThi_a = (uint32_t)__cvta_generic_to_shared(WAT_HI) + (uint32_t)(nq * 32 * 72 * 2);

    for (int row = blockIdx.x; row < NROW; row += GRID_PERS) {
        const int b = row >> 8;
        const float* rrow = r + (size_t)row * (TT * 9);

        // ---- stage QA + r tile 0 -> RT[0]; prefetch tile 1 ----
        if (tid < 64) QA[tid] = g_proj[row * 128 + tid];
        float4 rpre;
        if (tid < 144) {
            rpre = ((const float4*)rrow)[tid];
            __nv_bfloat16* RT0_HI = (__nv_bfloat16*)(sb + SO_RT);
            __nv_bfloat16* RT0_LO = RT0_HI + 1536;
            const int e0 = tid * 4;
#pragma unroll
            for (int u = 0; u < 4; u++) {
                const int e = e0 + u, j = e / 9, d = e - j * 9;
                __nv_bfloat16 hi, lo;
                split1(((const float*)&rpre)[u], hi, lo);
                RT0_HI[j * 24 + d] = hi;
                RT0_LO[j * 24 + d] = lo;
            }
            rpre = ((const float4*)(rrow + 576))[tid];   // tile 1
        }
        __syncthreads();

        float l8[8], a8[8];
#pragma unroll
        for (int s = 0; s < 8; s++) { l8[s] = 0.f; a8[s] = 0.f; }

        for (int jt = 0; jt < 4; jt++) {
            const int j0 = jt * 64;
            const int p = jt & 1;
            const uint32_t rt_rd  = RT_a + (uint32_t)(p * RT_BUF);
            const uint32_t s1x_hi = S1X_a + (uint32_t)(p * S1X_BUF);
            const uint32_t s1x_lo = s1x_hi + 9216u;
            __nv_bfloat16* S1Xw_HI = (__nv_bfloat16*)(sb + SO_S1X + p * S1X_BUF);
            __nv_bfloat16* S1Xw_LO = S1Xw_HI + 4608;
            float* VJp = (float*)(sb + SO_VJ + p * VJ_BUF);

            // ---- Phase A (regs, every warp): H = relu(r @ W1F + B1F) ----
            uint32_t Hhi[2][4], Hlo[2][4];
            {
                uint32_t rahi[4], ralo[4];
                ldsm_x4(rahi[0], rahi[1], rahi[2], rahi[3], rt_rd + (uint32_t)aoff24 * 2u);
                ldsm_x4(ralo[0], ralo[1], ralo[2], ralo[3], rt_rd + 3072u + (uint32_t)aoff24 * 2u);
                float accA[4][4];
#pragma unroll
                for (int t = 0; t < 4; t++)
#pragma unroll
                    for (int u = 0; u < 4; u++) accA[t][u] = 0.f;
                MMA_GROUP4(accA, 0, rahi, ralo, W1Thi_a, W1Tlo_a, 24, 0);
#pragma unroll
                for (int ks = 0; ks < 2; ks++) {
                    const int t0 = 2 * ks, t1 = 2 * ks + 1;
                    const float2 bb0 = *(const float2*)(B1F + t0 * 8 + 2 * tig);
                    const float2 bb1 = *(const float2*)(B1F + t1 * 8 + 2 * tig);
                    split2(fmaxf(accA[t0][0] + bb0.x, 0.f), fmaxf(accA[t0][1] + bb0.y, 0.f),
                           Hhi[ks][0], Hlo[ks][0]);
                    split2(fmaxf(accA[t0][2] + bb0.x, 0.f), fmaxf(accA[t0][3] + bb0.y, 0.f),
                           Hhi[ks][1], Hlo[ks][1]);
                    split2(fmaxf(accA[t1][0] + bb1.x, 0.f), fmaxf(accA[t1][1] + bb1.y, 0.f),
                           Hhi[ks][2], Hlo[ks][2]);
                    split2(fmaxf(accA[t1][2] + bb1.x, 0.f), fmaxf(accA[t1][3] + bb1.y, 0.f),
                           Hhi[ks][3], Hlo[ks][3]);
                }
            }

            // ---- store next r tile into RT[p^1] BEFORE arrives ----
            if (jt < 3 && tid < 144) {
                __nv_bfloat16* RTw_HI = (__nv_bfloat16*)(sb + SO_RT + (p ^ 1) * RT_BUF);
                __nv_bfloat16* RTw_LO = RTw_HI + 1536;
                const int e0 = tid * 4;
#pragma unroll
                for (int u = 0; u < 4; u++) {
                    const int e = e0 + u, j = e / 9, d = e - j * 9;
                    __nv_bfloat16 hi, lo;
                    split1(((const float*)&rpre)[u], hi, lo);
                    RTw_HI[j * 24 + d] = hi;
                    RTw_LO[j * 24 + d] = lo;
                }
                if (jt < 2)
                    rpre = ((const float4*)(rrow + (j0 + 128) * 9))[tid];  // tile jt+2
            }

            float accD[4][4];
#pragma unroll
            for (int t = 0; t < 4; t++)
#pragma unroll
                for (int u = 0; u < 4; u++) accD[t][u] = 0.f;
            float vjk[4][4];                   // warps 4-7: vj cols 32..63

            if (wid < 4) {
                // ---- warps 0-3: S1 = relu(H@W2P + qa - ka + b1a) ----
                float accS[8][4];
#pragma unroll
                for (int t = 0; t < 8; t++)
#pragma unroll
                    for (int u = 0; u < 4; u++) accS[t][u] = 0.f;
#pragma unroll
                for (int g = 0; g < 2; g++)
#pragma unroll
                    for (int ks = 0; ks < 2; ks++)
                        MMA_GROUP4(accS, g * 4, Hhi[ks], Hlo[ks], WS1hi_a, WS1lo_a, 40, ks * 16);
                const float* ka0p = &g_proj[(b * TT + j0 + r0) * 128 + 64];
                const float* ka1p = &g_proj[(b * TT + j0 + r0 + 8) * 128 + 64];
                uint32_t s1hi[4][4], s1lo[4][4];
#pragma unroll
                for (int kg = 0; kg < 4; kg++) {
#pragma unroll
                    for (int half = 0; half < 2; half++) {
                        const int tt = 2 * kg + half;
                        const int c = tt * 8 + 2 * tig;
                        const float2 qa2 = *(const float2*)(QA + c);
                        const float2 ba2 = *(const float2*)(B1A + c);
                        const float2 ka0 = *(const float2*)(ka0p + c);
                        const float2 ka1 = *(const float2*)(ka1p + c);
                        const float s00 = fmaxf(accS[tt][0] + qa2.x - ka0.x + ba2.x, 0.f);
                        const float s01 = fmaxf(accS[tt][1] + qa2.y - ka0.y + ba2.y, 0.f);
                        const float s10 = fmaxf(accS[tt][2] + qa2.x - ka1.x + ba2.x, 0.f);
                        const float s11 = fmaxf(accS[tt][3] + qa2.y - ka1.y + ba2.y, 0.f);
                        uint32_t hi0, lo0, hi1, lo1;
                        split2(s00, s01, hi0, lo0);
                        split2(s10, s11, hi1, lo1);
                        s1hi[kg][half * 2] = hi0;     s1lo[kg][half * 2] = lo0;
                        s1hi[kg][half * 2 + 1] = hi1; s1lo[kg][half * 2 + 1] = lo1;
                        *(uint32_t*)(S1Xw_HI + r0 * 72 + c) = hi0;
                        *(uint32_t*)(S1Xw_LO + r0 * 72 + c) = lo0;
                        *(uint32_t*)(S1Xw_HI + (r0 + 8) * 72 + c) = hi1;
                        *(uint32_t*)(S1Xw_LO + (r0 + 8) * 72 + c) = lo1;
                    }
                }
                BAR_ARRIVE(1);                 // S1X[p] published
                // Sim (2-term) immediately from own fragments
#pragma unroll
                for (int ks = 0; ks < 4; ks++)
                    MMA_GROUP4_2T(accD, 0, s1hi[ks], s1lo[ks], WAThi_a, 72, ks * 16);
                BAR_SYNC(2);                   // wait for VJ[p]
            } else {
                // ---- warps 4-7: RE = H@W2T + b2f ; vj = RE + vg ----
                float accR[8][4];
#pragma unroll
                for (int t = 0; t < 8; t++)
#pragma unroll
                    for (int u = 0; u < 4; u++) accR[t][u] = 0.f;
#pragma unroll
                for (int g = 0; g < 2; g++)
#pragma unroll
                    for (int ks = 0; ks < 2; ks++)
                        MMA_GROUP4(accR, g * 4, Hhi[ks], Hlo[ks], WREhi_a, WRElo_a, 40, ks * 16);
                const float* v0p = &g_qkv[(b * TT + j0 + r0) * 192 + 128];
                const float* v1p = &g_qkv[(b * TT + j0 + r0 + 8) * 192 + 128];
#pragma unroll
                for (int tt = 0; tt < 8; tt++) {
                    const int c = tt * 8 + 2 * tig;
                    const float2 bf2 = *(const float2*)(B2F + c);
                    const float2 vg0 = *(const float2*)(v0p + c);
                    const float2 vg1 = *(const float2*)(v1p + c);
                    const float j00 = accR[tt][0] + bf2.x + vg0.x;
                    const float j01 = accR[tt][1] + bf2.y + vg0.y;
                    const float j10 = accR[tt][2] + bf2.x + vg1.x;
                    const float j11 = accR[tt][3] + bf2.y + vg1.y;
                    if (tt < 4) {            // cols 0..31 -> smem for warps 0-3
                        *(float2*)(VJp + r0 * 36 + c) = make_float2(j00, j01);
                        *(float2*)(VJp + (r0 + 8) * 36 + c) = make_float2(j10, j11);
                    } else {                 // cols 32..63 stay local
                        vjk[tt - 4][0] = j00; vjk[tt - 4][1] = j01;
                        vjk[tt - 4][2] = j10; vjk[tt - 4][3] = j11;
                    }
                }
                BAR_ARRIVE(2);                 // VJ[p] published
                BAR_SYNC(1);                   // wait for S1X[p]
                uint32_t s1hi[4][4], s1lo[4][4];
#pragma unroll
                for (int ks = 0; ks < 4; ks++) {
                    ldsm_x4(s1hi[ks][0], s1hi[ks][1], s1hi[ks][2], s1hi[ks][3],
                            s1x_hi + (uint32_t)(aoff72 + ks * 16) * 2u);
                    ldsm_x4(s1lo[ks][0], s1lo[ks][1], s1lo[ks][2], s1lo[ks][3],
                            s1x_lo + (uint32_t)(aoff72 + ks * 16) * 2u);
                }
#pragma unroll
                for (int ks = 0; ks < 4; ks++)
                    MMA_GROUP4_2T(accD, 0, s1hi[ks], s1lo[ks], WAThi_a, 72, ks * 16);
            }

            // ---- softmax accumulate in fragment layout (no barrier) ----
#pragma unroll
            for (int tt = 0; tt < 4; tt++) {
                float vj00, vj01, vj10, vj11;
                if (wid < 4) {
                    const int c = tt * 8 + 2 * tig;
                    const float2 a0v = *(const float2*)(VJp + r0 * 36 + c);
                    const float2 a1v = *(const float2*)(VJp + (r0 + 8) * 36 + c);
                    vj00 = a0v.x; vj01 = a0v.y; vj10 = a1v.x; vj11 = a1v.y;
                } else {
                    vj00 = vjk[tt][0]; vj01 = vjk[tt][1];
                    vj10 = vjk[tt][2]; vj11 = vjk[tt][3];
                }
                const float e00 = __expf(accD[tt][0]);
                const float e01 = __expf(accD[tt][1]);
                const float e10 = __expf(accD[tt][2]);
                const float e11 = __expf(accD[tt][3]);
                l8[tt * 2 + 0] += e00 + e10;
                l8[tt * 2 + 1] += e01 + e11;
                a8[tt * 2 + 0] += e00 * vj00 + e10 * vj10;
                a8[tt * 2 + 1] += e01 * vj01 + e11 * vj11;
            }
            // no trailing barrier: all cross-tile hazards are buffer-separated
        }

        // ---- cross-warp combine (CL/CA alias S1X[0] space) ----
        __syncthreads();           // all tile reads (S1X/VJ/RT) complete
        {
            const int p = wmod * 8 + gid;
#pragma unroll
            for (int tt = 0; tt < 4; tt++) {
#pragma unroll
                for (int u = 0; u < 2; u++) {
                    const int c = nq * 32 + tt * 8 + 2 * tig + u;
                    CL[p * 65 + c] = l8[tt * 2 + u];
                    CA[p * 65 + c] = a8[tt * 2 + u];
                }
            }
        }
        __syncthreads();
        if (tid < 64) {
            float L = 0.f, A = 0.f;
#pragma unroll
            for (int pp = 0; pp < 32; pp++) {
                L += CL[pp * 65 + tid];
                A += CA[pp * 65 + tid];
            }
            out[row * 64 + tid] = A / L;
        }
        __syncthreads();           // CL/CA reads done before next row's writes
    }
}

// ---------------------------------------------------------------------------
extern "C" void kernel_launch(void* const* d_in, const int* in_sizes, int n_in,
                              void* d_out, int out_size) {
    (void)in_sizes; (void)n_in; (void)out_size;
    const float* x      = (const float*)d_in[0];
    const float* r      = (const float*)d_in[1];
    const float* w_qkv  = (const float*)d_in[2];
    const float* tpr_w1 = (const float*)d_in[3];
    const float* tpr_b1 = (const float*)d_in[4];
    const float* bn_g   = (const float*)d_in[5];
    const float* bn_b   = (const float*)d_in[6];
    const float* bn_m   = (const float*)d_in[7];
    const float* bn_v   = (const float*)d_in[8];
    const float* tpr_w2 = (const float*)d_in[9];
    const float* tpr_b2 = (const float*)d_in[10];
    const float* aw1    = (const float*)d_in[11];
    const float* ab1    = (const float*)d_in[12];
    const float* aw2    = (const float*)d_in[13];
    float* out = (float*)d_out;

    cudaFuncSetAttribute(va_kernel, cudaFuncAttributeMaxDynamicSharedMemorySize,
                         SMEM_BYTES);

    prelude_kernel<<<129, 256>>>(x, w_qkv, aw1, tpr_w2, tpr_b2, ab1);
    va_kernel<<<GRID_PERS, 256, SMEM_BYTES>>>(r, tpr_w1, tpr_b1, bn_g, bn_b, bn_m,
                                              bn_v, tpr_w2, tpr_b2, aw2, out);
}

// round 17
// speedup vs baseline: 1.3265x; 1.0319x over previous
#include <cuda_runtime.h>
#include <cuda_bf16.h>
#include <math.h>
#include <stdint.h>

#define TT 256
#define NROW 2048            // B*T
#define BN_EPS 1e-5f
#define GRID_PERS 296        // 148 SMs x 2 CTAs = one full wave

// scratch
__device__ float g_qkv[NROW * 192];    // only v-part (cols 128..191) is populated/used
__device__ float g_proj[NROW * 128];   // qA|kA per row  ({q,k}@attn_w1)
__device__ float g_w2p[32 * 64];       // tpr_w2 @ attn_w1
__device__ float g_b1a[64];            // tpr_b2 @ attn_w1 + attn_b1

// ---------------------------------------------------------------------------
// Fused prelude: blocks 0..127 -> qkv+proj for 16 rows each; block 128 -> w2p
// ---------------------------------------------------------------------------
__global__ __launch_bounds__(256) void prelude_kernel(
    const float* __restrict__ x, const float* __restrict__ w_qkv,
    const float* __restrict__ aw1, const float* __restrict__ tpr_w2,
    const float* __restrict__ tpr_b2, const float* __restrict__ ab1)
{
    const int tid = threadIdx.x;

    __shared__ float sA[4096];         // aw1 (block 128) | unused others
    __shared__ float xs[16 * 128];     // 16 rows of x    | w2s (block 128, first 2048)
    __shared__ float qs[16 * 192];     // 16 rows of qkv

    if (blockIdx.x == 128) {
        // ---- W2P = tpr_w2 @ attn_w1 ; b1a = tpr_b2 @ attn_w1 + attn_b1 ----
        float* w2s = xs;               // reuse xs region (2048 floats)
        for (int i = tid; i < 2048; i += 256) w2s[i] = tpr_w2[i];
        for (int i = tid; i < 4096; i += 256) sA[i] = aw1[i];
        __syncthreads();
#pragma unroll
        for (int kk = 0; kk < 8; kk++) {
            const int idx = tid + kk * 256;        // 0..2047
            const int h = idx >> 6, c = idx & 63;
            float acc = 0.f;
#pragma unroll 8
            for (int d = 0; d < 64; d++) acc += w2s[h * 64 + d] * sA[d * 64 + c];
            g_w2p[idx] = acc;
        }
        if (tid < 64) {
            float accb = ab1[tid];
#pragma unroll 8
            for (int d = 0; d < 64; d++) accb += tpr_b2[d] * sA[d * 64 + tid];
            g_b1a[tid] = accb;
        }
        return;
    }

    const int r0 = blockIdx.x * 16;

    // stage x rows
    for (int idx = tid; idx < 16 * 128; idx += 256)
        xs[idx] = x[(size_t)r0 * 128 + idx];
    __syncthreads();

    // qkv: 192 cols, w_qkv read ONCE per block
    if (tid < 192) {
        const int col = tid;
        float acc[16];
#pragma unroll
        for (int rr = 0; rr < 16; rr++) acc[rr] = 0.f;
#pragma unroll 8
        for (int d = 0; d < 128; d++) {
            const float wv = w_qkv[d * 192 + col];
#pragma unroll
            for (int rr = 0; rr < 16; rr++)
                acc[rr] += xs[rr * 128 + d] * wv;
        }
#pragma unroll
        for (int rr = 0; rr < 16; rr++) {
            qs[rr * 192 + col] = acc[rr];
            if (col >= 128)                       // only v needed downstream
                g_qkv[(size_t)(r0 + rr) * 192 + col] = acc[rr];
        }
    }
    __syncthreads();

    // proj: qA|kA = {q,k} @ aw1
    {
        const int col = tid & 63;
        const int half = (tid >> 6) & 1;          // 0 = q, 1 = k
        const int rg = tid >> 7;                  // row group (8 rows)
        float acc8[8];
#pragma unroll
        for (int rr = 0; rr < 8; rr++) acc8[rr] = 0.f;
#pragma unroll 8
        for (int d = 0; d < 64; d++) {
            const float av = aw1[d * 64 + col];
#pragma unroll
            for (int rr = 0; rr < 8; rr++)
                acc8[rr] += qs[(rg * 8 + rr) * 192 + half * 64 + d] * av;
        }
#pragma unroll
        for (int rr = 0; rr < 8; rr++)
            g_proj[(size_t)(r0 + rg * 8 + rr) * 128 + half * 64 + col] = acc8[rr];
    }
}

// ---------------------------------------------------------------------------
// helpers
// ---------------------------------------------------------------------------
__device__ __forceinline__ void mma_bf16(float* d, const uint32_t* a,
                                         uint32_t b0, uint32_t b1) {
    asm volatile(
        "mma.sync.aligned.m16n8k16.row.col.f32.bf16.bf16.f32 "
        "{%0,%1,%2,%3}, {%4,%5,%6,%7}, {%8,%9}, {%0,%1,%2,%3};"
        : "+f"(d[0]), "+f"(d[1]), "+f"(d[2]), "+f"(d[3])
        : "r"(a[0]), "r"(a[1]), "r"(a[2]), "r"(a[3]), "r"(b0), "r"(b1));
}

__device__ __forceinline__ void ldsm_x4(uint32_t& r0, uint32_t& r1,
                                        uint32_t& r2, uint32_t& r3, uint32_t addr) {
    asm volatile("ldmatrix.sync.aligned.m8n8.x4.shared.b16 {%0,%1,%2,%3}, [%4];"
                 : "=r"(r0), "=r"(r1), "=r"(r2), "=r"(r3) : "r"(addr));
}

#define BAR_ARRIVE(id) asm volatile("bar.arrive %0, %1;" :: "r"(id), "r"(256) : "memory")
#define BAR_SYNC(id)   asm volatile("bar.sync %0, %1;"   :: "r"(id), "r"(256) : "memory")

__device__ __forceinline__ uint32_t b2u(__nv_bfloat162 v) {
    return *reinterpret_cast<uint32_t*>(&v);
}

__device__ __forceinline__ void split2(float x, float y, uint32_t& hi, uint32_t& lo) {
    __nv_bfloat16 hx = __float2bfloat16_rn(x);
    __nv_bfloat16 hy = __float2bfloat16_rn(y);
    float rx = x - __bfloat162float(hx);
    float ry = y - __bfloat162float(hy);
    __nv_bfloat162 h2; h2.x = hx; h2.y = hy;
    hi = b2u(h2);
    lo = b2u(__floats2bfloat162_rn(rx, ry));
}

__device__ __forceinline__ void split1(float x, __nv_bfloat16& hi, __nv_bfloat16& lo) {
    hi = __float2bfloat16_rn(x);
    lo = __float2bfloat16_rn(x - __bfloat162float(hi));
}

// 4 n-tiles, 3-term bf16x3 split, dependency distance 4 (12 MMAs)
#define MMA_GROUP4(ACC, T0, AH, AL, WHI, WLO, STRIDE, KOFF)                       \
    do {                                                                          \
        uint32_t bh[8], bl[8];                                                    \
        ldsm_x4(bh[0], bh[1], bh[2], bh[3],                                       \
                WHI + (uint32_t)((((T0) * 8 + brow) * (STRIDE)) + (KOFF) + bcol) * 2u); \
        ldsm_x4(bh[4], bh[5], bh[6], bh[7],                                       \
                WHI + (uint32_t)(((((T0) + 2) * 8 + brow) * (STRIDE)) + (KOFF) + bcol) * 2u); \
        ldsm_x4(bl[0], bl[1], bl[2], bl[3],                                       \
                WLO + (uint32_t)((((T0) * 8 + brow) * (STRIDE)) + (KOFF) + bcol) * 2u); \
        ldsm_x4(bl[4], bl[5], bl[6], bl[7],                                       \
                WLO + (uint32_t)(((((T0) + 2) * 8 + brow) * (STRIDE)) + (KOFF) + bcol) * 2u); \
        mma_bf16(ACC[(T0) + 0], AH, bh[0], bh[1]);                                \
        mma_bf16(ACC[(T0) + 1], AH, bh[2], bh[3]);                                \
        mma_bf16(ACC[(T0) + 2], AH, bh[4], bh[5]);                                \
        mma_bf16(ACC[(T0) + 3], AH, bh[6], bh[7]);                                \
        mma_bf16(ACC[(T0) + 0], AH, bl[0], bl[1]);                                \
        mma_bf16(ACC[(T0) + 1], AH, bl[2], bl[3]);                                \
        mma_bf16(ACC[(T0) + 2], AH, bl[4], bl[5]);                                \
        mma_bf16(ACC[(T0) + 3], AH, bl[6], bl[7]);                                \
        mma_bf16(ACC[(T0) + 0], AL, bh[0], bh[1]);                                \
        mma_bf16(ACC[(T0) + 1], AL, bh[2], bh[3]);                                \
        mma_bf16(ACC[(T0) + 2], AL, bh[4], bh[5]);                                \
        mma_bf16(ACC[(T0) + 3], AL, bh[6], bh[7]);                                \
    } while (0)

// 4 n-tiles, 2-term split (A split, weight hi only): 2 ldsm_x4, 8 MMAs.
// Error model validated R16: dropped weight-lo term contributes ~2^-9 relative
// of that GEMM's product magnitude. Used for S1, RE, Sim GEMMs.
#define MMA_GROUP4_2T(ACC, T0, AH, AL, WHI, STRIDE, KOFF)                         \
    do {                                                                          \
        uint32_t bh[8];                                                           \
        ldsm_x4(bh[0], bh[1], bh[2], bh[3],                                       \
                WHI + (uint32_t)((((T0) * 8 + brow) * (STRIDE)) + (KOFF) + bcol) * 2u); \
        ldsm_x4(bh[4], bh[5], bh[6], bh[7],                                       \
                WHI + (uint32_t)(((((T0) + 2) * 8 + brow) * (STRIDE)) + (KOFF) + bcol) * 2u); \
        mma_bf16(ACC[(T0) + 0], AH, bh[0], bh[1]);                                \
        mma_bf16(ACC[(T0) + 1], AH, bh[2], bh[3]);                                \
        mma_bf16(ACC[(T0) + 2], AH, bh[4], bh[5]);                                \
        mma_bf16(ACC[(T0) + 3], AH, bh[6], bh[7]);                                \
        mma_bf16(ACC[(T0) + 0], AL, bh[0], bh[1]);                                \
        mma_bf16(ACC[(T0) + 1], AL, bh[2], bh[3]);                                \
        mma_bf16(ACC[(T0) + 2], AL, bh[4], bh[5]);                                \
        mma_bf16(ACC[(T0) + 3], AL, bh[6], bh[7]);                                \
    } while (0)

// ---------------------------------------------------------------------------
// Shared memory byte offsets (16B aligned). S1X / RT / VJ double-buffered.
// (WRE_LO / WS1_LO / WAT_LO regions unused — 2-term GEMMs.)
// ---------------------------------------------------------------------------
#define SO_WRE_HI 0          // [64][40] bf16  W2T^T
#define SO_WRE_LO 5120       // unused
#define SO_WS1_HI 10240      // [64][40] bf16  W2P^T
#define SO_WS1_LO 15360      // unused
#define SO_WAT_HI 20480      // [64][72] bf16  W2A^T
#define SO_WAT_LO 29696      // unused
#define SO_S1X    38912      // [2] x { HI 9216 | LO 9216 } = 36864 (ends 75776)
#define S1X_BUF   18432
#define SO_CL     38912      // combine partials (alias S1X[0]; post-loop only)
#define SO_CA     47232      // 32*65 fp32 each
#define SO_RT     75776      // [2] x { HI 3072 | LO 3072 } = 12288 (ends 88064)
#define RT_BUF    6144
#define SO_W1T_HI 88064      // [32][24] bf16
#define SO_W1T_LO 89600      // ends 91136
#define SO_VJ     91136      // [2] x [64][36] fp32 = 18432 (ends 109568)
#define VJ_BUF    9216
#define SO_B1F    109568     // 32 fp32
#define SO_B2F    109696     // 64
#define SO_B1A    109952     // 64
#define SO_QA     110208     // 64
#define SMEM_BYTES 110464

__global__ __launch_bounds__(256, 2) void va_kernel(
    const float* __restrict__ r,
    const float* __restrict__ tpr_w1, const float* __restrict__ tpr_b1,
    const float* __restrict__ bn_g, const float* __restrict__ bn_b,
    const float* __restrict__ bn_m, const float* __restrict__ bn_v,
    const float* __restrict__ tpr_w2, const float* __restrict__ tpr_b2,
    const float* __restrict__ aw2, float* __restrict__ out)
{
    extern __shared__ __align__(16) char sb[];
    __nv_bfloat16* W1T_HI = (__nv_bfloat16*)(sb + SO_W1T_HI);
    __nv_bfloat16* W1T_LO = (__nv_bfloat16*)(sb + SO_W1T_LO);
    __nv_bfloat16* WRE_HI = (__nv_bfloat16*)(sb + SO_WRE_HI);
    __nv_bfloat16* WS1_HI = (__nv_bfloat16*)(sb + SO_WS1_HI);
    __nv_bfloat16* WAT_HI = (__nv_bfloat16*)(sb + SO_WAT_HI);
    float* CL   = (float*)(sb + SO_CL);
    float* CA   = (float*)(sb + SO_CA);
    float* B1F  = (float*)(sb + SO_B1F);
    float* B2F  = (float*)(sb + SO_B2F);
    float* B1A  = (float*)(sb + SO_B1A);
    float* QA   = (float*)(sb + SO_QA);

    const int tid = threadIdx.x;
    const int wid = tid >> 5, lane = tid & 31;
    const int gid = lane >> 2, tig = lane & 3;
    const int arow = lane & 7, asel = lane >> 3;

    // ---- stage weights ONCE per persistent CTA ----
    for (int idx = tid; idx < 6144; idx += 256)
        ((__nv_bfloat16*)(sb + SO_RT))[idx] = __nv_bfloat16(0.f);
    for (int idx = tid; idx < 32 * 24; idx += 256) { W1T_HI[idx] = __nv_bfloat16(0.f); W1T_LO[idx] = __nv_bfloat16(0.f); }
    if (tid < 32) {
        float sc = bn_g[tid] * rsqrtf(bn_v[tid] + BN_EPS);
        B1F[tid] = (tpr_b1[tid] - bn_m[tid]) * sc + bn_b[tid];
    }
    if (tid < 64) {
        B2F[tid] = tpr_b2[tid];
        B1A[tid] = g_b1a[tid];
    }
    __syncthreads();
    for (int idx = tid; idx < 288; idx += 256) {      // BN-folded W1^T (3-term)
        const int d = idx >> 5, n = idx & 31;
        const float sc = bn_g[n] * rsqrtf(bn_v[n] + BN_EPS);
        __nv_bfloat16 hi, lo;
        split1(tpr_w1[idx] * sc, hi, lo);
        W1T_HI[n * 24 + d] = hi;
        W1T_LO[n * 24 + d] = lo;
    }
    for (int idx = tid; idx < 2048; idx += 256) {     // W2T^T, W2P^T hi only (stride 40)
        const int n = idx >> 5, k = idx & 31;
        WRE_HI[n * 40 + k] = __float2bfloat16_rn(tpr_w2[k * 64 + n]);
        WS1_HI[n * 40 + k] = __float2bfloat16_rn(g_w2p[k * 64 + n]);
    }
    for (int idx = tid; idx < 4096; idx += 256) {     // W2A^T hi only (stride 72)
        const int n = idx >> 6, k = idx & 63;
        WAT_HI[n * 72 + k] = __float2bfloat16_rn(aw2[k * 64 + n]);
    }

    const int wmod = wid & 3;            // m-tile (warps w and w+4 share it)
    const int nq = wid >> 2;             // n-half owner for Sim phase
    const int m0 = wmod * 16;
    const int r0 = m0 + gid;
    const int brow = arow + (asel >> 1) * 8;
    const int bcol = (asel & 1) * 8;
    const int aoff24 = (m0 + arow + (asel & 1) * 8) * 24 + (asel >> 1) * 8;
    const int aoff72 = (m0 + arow + (asel & 1) * 8) * 72 + (asel >> 1) * 8;

    const uint32_t RT_a    = (uint32_t)__cvta_generic_to_shared(sb + SO_RT);
    const uint32_t S1X_a   = (uint32_t)__cvta_generic_to_shared(sb + SO_S1X);
    const uint32_t W1Thi_a = (uint32_t)__cvta_generic_to_shared(W1T_HI);
    const uint32_t W1Tlo_a = (uint32_t)__cvta_generic_to_shared(W1T_LO);
    const uint32_t WS1hi_a = (uint32_t)__cvta_generic_to_shared(WS1_HI);
    const uint32_t WREhi_a = (uint32_t)__cvta_generic_to_shared(WRE_HI);
    const uint32_t WAThi_a = (uint32_t)__cvta_generic_to_shared(WAT_HI) + (uint32_t)(nq * 32 * 72 * 2);

    for (int row = blockIdx.x; row < NROW; row += GRID_PERS) {
        const int b = row >> 8;
        const float* rrow = r + (size_t)row * (TT * 9);

        // ---- stage QA + r tile 0 -> RT[0]; prefetch tile 1 ----
        if (tid < 64) QA[tid] = g_proj[row * 128 + tid];
        float4 rpre;
        if (tid < 144) {
            rpre = ((const float4*)rrow)[tid];
            __nv_bfloat16* RT0_HI = (__nv_bfloat16*)(sb + SO_RT);
            __nv_bfloat16* RT0_LO = RT0_HI + 1536;
            const int e0 = tid * 4;
#pragma unroll
            for (int u = 0; u < 4; u++) {
                const int e = e0 + u, j = e / 9, d = e - j * 9;
                __nv_bfloat16 hi, lo;
                split1(((const float*)&rpre)[u], hi, lo);
                RT0_HI[j * 24 + d] = hi;
                RT0_LO[j * 24 + d] = lo;
            }
            rpre = ((const float4*)(rrow + 576))[tid];   // tile 1
        }
        __syncthreads();

        float l8[8], a8[8];
#pragma unroll
        for (int s = 0; s < 8; s++) { l8[s] = 0.f; a8[s] = 0.f; }

        for (int jt = 0; jt < 4; jt++) {
            const int j0 = jt * 64;
            const int p = jt & 1;
            const uint32_t rt_rd  = RT_a + (uint32_t)(p * RT_BUF);
            const uint32_t s1x_hi = S1X_a + (uint32_t)(p * S1X_BUF);
            const uint32_t s1x_lo = s1x_hi + 9216u;
            __nv_bfloat16* S1Xw_HI = (__nv_bfloat16*)(sb + SO_S1X + p * S1X_BUF);
            __nv_bfloat16* S1Xw_LO = S1Xw_HI + 4608;
            float* VJp = (float*)(sb + SO_VJ + p * VJ_BUF);

            // ---- Phase A (regs, every warp): H = relu(r @ W1F + B1F), 3-term ----
            uint32_t Hhi[2][4], Hlo[2][4];
            {
                uint32_t rahi[4], ralo[4];
                ldsm_x4(rahi[0], rahi[1], rahi[2], rahi[3], rt_rd + (uint32_t)aoff24 * 2u);
                ldsm_x4(ralo[0], ralo[1], ralo[2], ralo[3], rt_rd + 3072u + (uint32_t)aoff24 * 2u);
                float accA[4][4];
#pragma unroll
                for (int t = 0; t < 4; t++)
#pragma unroll
                    for (int u = 0; u < 4; u++) accA[t][u] = 0.f;
                MMA_GROUP4(accA, 0, rahi, ralo, W1Thi_a, W1Tlo_a, 24, 0);
#pragma unroll
                for (int ks = 0; ks < 2; ks++) {
                    const int t0 = 2 * ks, t1 = 2 * ks + 1;
                    const float2 bb0 = *(const float2*)(B1F + t0 * 8 + 2 * tig);
                    const float2 bb1 = *(const float2*)(B1F + t1 * 8 + 2 * tig);
                    split2(fmaxf(accA[t0][0] + bb0.x, 0.f), fmaxf(accA[t0][1] + bb0.y, 0.f),
                           Hhi[ks][0], Hlo[ks][0]);
                    split2(fmaxf(accA[t0][2] + bb0.x, 0.f), fmaxf(accA[t0][3] + bb0.y, 0.f),
                           Hhi[ks][1], Hlo[ks][1]);
                    split2(fmaxf(accA[t1][0] + bb1.x, 0.f), fmaxf(accA[t1][1] + bb1.y, 0.f),
                           Hhi[ks][2], Hlo[ks][2]);
                    split2(fmaxf(accA[t1][2] + bb1.x, 0.f), fmaxf(accA[t1][3] + bb1.y, 0.f),
                           Hhi[ks][3], Hlo[ks][3]);
                }
            }

            // ---- store next r tile into RT[p^1] BEFORE arrives ----
            if (jt < 3 && tid < 144) {
                __nv_bfloat16* RTw_HI = (__nv_bfloat16*)(sb + SO_RT + (p ^ 1) * RT_BUF);
                __nv_bfloat16* RTw_LO = RTw_HI + 1536;
                const int e0 = tid * 4;
#pragma unroll
                for (int u = 0; u < 4; u++) {
                    const int e = e0 + u, j = e / 9, d = e - j * 9;
                    __nv_bfloat16 hi, lo;
                    split1(((const float*)&rpre)[u], hi, lo);
                    RTw_HI[j * 24 + d] = hi;
                    RTw_LO[j * 24 + d] = lo;
                }
                if (jt < 2)
                    rpre = ((const float4*)(rrow + (j0 + 128) * 9))[tid];  // tile jt+2
            }

            float accD[4][4];
#pragma unroll
            for (int t = 0; t < 4; t++)
#pragma unroll
                for (int u = 0; u < 4; u++) accD[t][u] = 0.f;
            float vjk[4][4];                   // warps 4-7: vj cols 32..63

            if (wid < 4) {
                // ---- warps 0-3: S1 = relu(H@W2P + qa - ka + b1a), 2-term ----
                float accS[8][4];
#pragma unroll
                for (int t = 0; t < 8; t++)
#pragma unroll
                    for (int u = 0; u < 4; u++) accS[t][u] = 0.f;
#pragma unroll
                for (int g = 0; g < 2; g++)
#pragma unroll
                    for (int ks = 0; ks < 2; ks++)
                        MMA_GROUP4_2T(accS, g * 4, Hhi[ks], Hlo[ks], WS1hi_a, 40, ks * 16);
                const float* ka0p = &g_proj[(b * TT + j0 + r0) * 128 + 64];
                const float* ka1p = &g_proj[(b * TT + j0 + r0 + 8) * 128 + 64];
                uint32_t s1hi[4][4], s1lo[4][4];
#pragma unroll
                for (int kg = 0; kg < 4; kg++) {
#pragma unroll
                    for (int half = 0; half < 2; half++) {
                        const int tt = 2 * kg + half;
                        const int c = tt * 8 + 2 * tig;
                        const float2 qa2 = *(const float2*)(QA + c);
                        const float2 ba2 = *(const float2*)(B1A + c);
                        const float2 ka0 = *(const float2*)(ka0p + c);
                        const float2 ka1 = *(const float2*)(ka1p + c);
                        const float s00 = fmaxf(accS[tt][0] + qa2.x - ka0.x + ba2.x, 0.f);
                        const float s01 = fmaxf(accS[tt][1] + qa2.y - ka0.y + ba2.y, 0.f);
                        const float s10 = fmaxf(accS[tt][2] + qa2.x - ka1.x + ba2.x, 0.f);
                        const float s11 = fmaxf(accS[tt][3] + qa2.y - ka1.y + ba2.y, 0.f);
                        uint32_t hi0, lo0, hi1, lo1;
                        split2(s00, s01, hi0, lo0);
                        split2(s10, s11, hi1, lo1);
                        s1hi[kg][half * 2] = hi0;     s1lo[kg][half * 2] = lo0;
                        s1hi[kg][half * 2 + 1] = hi1; s1lo[kg][half * 2 + 1] = lo1;
                        *(uint32_t*)(S1Xw_HI + r0 * 72 + c) = hi0;
                        *(uint32_t*)(S1Xw_LO + r0 * 72 + c) = lo0;
                        *(uint32_t*)(S1Xw_HI + (r0 + 8) * 72 + c) = hi1;
                        *(uint32_t*)(S1Xw_LO + (r0 + 8) * 72 + c) = lo1;
                    }
                }
                BAR_ARRIVE(1);                 // S1X[p] published
                // Sim (2-term) immediately from own fragments
#pragma unroll
                for (int ks = 0; ks < 4; ks++)
                    MMA_GROUP4_2T(accD, 0, s1hi[ks], s1lo[ks], WAThi_a, 72, ks * 16);
                BAR_SYNC(2);                   // wait for VJ[p]
            } else {
                // ---- warps 4-7: RE = H@W2T + b2f (2-term) ; vj = RE + vg ----
                float accR[8][4];
#pragma unroll
                for (int t = 0; t < 8; t++)
#pragma unroll
                    for (int u = 0; u < 4; u++) accR[t][u] = 0.f;
#pragma unroll
                for (int g = 0; g < 2; g++)
#pragma unroll
                    for (int ks = 0; ks < 2; ks++)
                        MMA_GROUP4_2T(accR, g * 4, Hhi[ks], Hlo[ks], WREhi_a, 40, ks * 16);
                const float* v0p = &g_qkv[(b * TT + j0 + r0) * 192 + 128];
                const float* v1p = &g_qkv[(b * TT + j0 + r0 + 8) * 192 + 128];
#pragma unroll
                for (int tt = 0; tt < 8; tt++) {
                    const int c = tt * 8 + 2 * tig;
                    const float2 bf2 = *(const float2*)(B2F + c);
                    const float2 vg0 = *(const float2*)(v0p + c);
                    const float2 vg1 = *(const float2*)(v1p + c);
                    const float j00 = accR[tt][0] + bf2.x + vg0.x;
                    const float j01 = accR[tt][1] + bf2.y + vg0.y;
                    const float j10 = accR[tt][2] + bf2.x + vg1.x;
                    const float j11 = accR[tt][3] + bf2.y + vg1.y;
                    if (tt < 4) {            // cols 0..31 -> smem for warps 0-3
                        *(float2*)(VJp + r0 * 36 + c) = make_float2(j00, j01);
                        *(float2*)(VJp + (r0 + 8) * 36 + c) = make_float2(j10, j11);
                    } else {                 // cols 32..63 stay local
                        vjk[tt - 4][0] = j00; vjk[tt - 4][1] = j01;
                        vjk[tt - 4][2] = j10; vjk[tt - 4][3] = j11;
                    }
                }
                BAR_ARRIVE(2);                 // VJ[p] published
                BAR_SYNC(1);                   // wait for S1X[p]
                uint32_t s1hi[4][4], s1lo[4][4];
#pragma unroll
                for (int ks = 0; ks < 4; ks++) {
                    ldsm_x4(s1hi[ks][0], s1hi[ks][1], s1hi[ks][2], s1hi[ks][3],
                            s1x_hi + (uint32_t)(aoff72 + ks * 16) * 2u);
                    ldsm_x4(s1lo[ks][0], s1lo[ks][1], s1lo[ks][2], s1lo[ks][3],
                            s1x_lo + (uint32_t)(aoff72 + ks * 16) * 2u);
                }
#pragma unroll
                for (int ks = 0; ks < 4; ks++)
                    MMA_GROUP4_2T(accD, 0, s1hi[ks], s1lo[ks], WAThi_a, 72, ks * 16);
            }

            // ---- softmax accumulate in fragment layout (no barrier) ----
#pragma unroll
            for (int tt = 0; tt < 4; tt++) {
                float vj00, vj01, vj10, vj11;
                if (wid < 4) {
                    const int c = tt * 8 + 2 * tig;
                    const float2 a0v = *(const float2*)(VJp + r0 * 36 + c);
                    const float2 a1v = *(const float2*)(VJp + (r0 + 8) * 36 + c);
                    vj00 = a0v.x; vj01 = a0v.y; vj10 = a1v.x; vj11 = a1v.y;
                } else {
                    vj00 = vjk[tt][0]; vj01 = vjk[tt][1];
                    vj10 = vjk[tt][2]; vj11 = vjk[tt][3];
                }
                const float e00 = __expf(accD[tt][0]);
                const float e01 = __expf(accD[tt][1]);
                const float e10 = __expf(accD[tt][2]);
                const float e11 = __expf(accD[tt][3]);
                l8[tt * 2 + 0] += e00 + e10;
                l8[tt * 2 + 1] += e01 + e11;
                a8[tt * 2 + 0] += e00 * vj00 + e10 * vj10;
                a8[tt * 2 + 1] += e01 * vj01 + e11 * vj11;
            }
            // no trailing barrier: all cross-tile hazards are buffer-separated
        }

        // ---- cross-warp combine (CL/CA alias S1X[0] space) ----
        __syncthreads();           // all tile reads (S1X/VJ/RT) complete
        {
            const int p = wmod * 8 + gid;
#pragma unroll
            for (int tt = 0; tt < 4; tt++) {
#pragma unroll
                for (int u = 0; u < 2; u++) {
                    const int c = nq * 32 + tt * 8 + 2 * tig + u;
                    CL[p * 65 + c] = l8[tt * 2 + u];
                    CA[p * 65 + c] = a8[tt * 2 + u];
                }
            }
        }
        __syncthreads();
        if (tid < 64) {
            float L = 0.f, A = 0.f;
#pragma unroll
            for (int pp = 0; pp < 32; pp++) {
                L += CL[pp * 65 + tid];
                A += CA[pp * 65 + tid];
            }
            out[row * 64 + tid] = A / L;
        }
        __syncthreads();           // CL/CA reads done before next row's writes
    }
}

// ---------------------------------------------------------------------------
extern "C" void kernel_launch(void* const* d_in, const int* in_sizes, int n_in,
                              void* d_out, int out_size) {
    (void)in_sizes; (void)n_in; (void)out_size;
    const float* x      = (const float*)d_in[0];
    const float* r      = (const float*)d_in[1];
    const float* w_qkv  = (const float*)d_in[2];
    const float* tpr_w1 = (const float*)d_in[3];
    const float* tpr_b1 = (const float*)d_in[4];
    const float* bn_g   = (const float*)d_in[5];
    const float* bn_b   = (const float*)d_in[6];
    const float* bn_m   = (const float*)d_in[7];
    const float* bn_v   = (const float*)d_in[8];
    const float* tpr_w2 = (const float*)d_in[9];
    const float* tpr_b2 = (const float*)d_in[10];
    const float* aw1    = (const float*)d_in[11];
    const float* ab1    = (const float*)d_in[12];
    const float* aw2    = (const float*)d_in[13];
    float* out = (float*)d_out;

    cudaFuncSetAttribute(va_kernel, cudaFuncAttributeMaxDynamicSharedMemorySize,
                         SMEM_BYTES);

    prelude_kernel<<<129, 256>>>(x, w_qkv, aw1, tpr_w2, tpr_b2, ab1);
    va_kernel<<<GRID_PERS, 256, SMEM_BYTES>>>(r, tpr_w1, tpr_b1, bn_g, bn_b, bn_m,
                                              bn_v, tpr_w2, tpr_b2, aw2, out);
}